// round 1
// baseline (speedup 1.0000x reference)
#include <cuda_runtime.h>
#include <cuda_bf16.h>

// CompactBilinearPooling: count-sketch (scatter-add) of x1, x2 into O=16384
// buckets, then circular convolution via FFT.
//
// Strategy: one CTA per batch row. Pack z = y1 + i*y2 in shared memory,
// single forward 16K complex FFT (DIF, natural->bitrev), Hermitian split +
// pointwise product done directly in bit-reversed positions, inverse FFT
// (DIT, bitrev->natural), write real part / N. No bit-reversal passes.

#define N_FFT   16384
#define LOG2N   14
#define HALF_N  8192
#define D_IN    4096
#define NTHREADS 1024

__global__ __launch_bounds__(NTHREADS, 1)
void cbp_fft_kernel(const float* __restrict__ x1,
                    const float* __restrict__ x2,
                    const int*   __restrict__ h1,
                    const float* __restrict__ s1,
                    float*       __restrict__ out)
{
    extern __shared__ float2 smem[];
    float2* z  = smem;            // [N_FFT]  work array (y1 + i*y2)
    float2* tw = smem + N_FFT;    // [HALF_N] twiddles exp(-2*pi*i*k/N)

    const int tid = threadIdx.x;
    const int b   = blockIdx.x;

    // --- twiddle table (args are exact multiples of 2^-13 -> sincospif exact-arg) ---
    #pragma unroll
    for (int k = tid; k < HALF_N; k += NTHREADS) {
        float s, c;
        sincospif(-2.0f * (float)k / (float)N_FFT, &s, &c);
        tw[k] = make_float2(c, s);
    }
    // --- zero the sketch accumulator ---
    #pragma unroll
    for (int i = tid; i < N_FFT; i += NTHREADS)
        z[i] = make_float2(0.0f, 0.0f);
    __syncthreads();

    // --- count-sketch scatter: z.x accumulates y1, z.y accumulates y2 ---
    {
        const float* x1r = x1 + (size_t)b * D_IN;
        const float* x2r = x2 + (size_t)b * D_IN;
        #pragma unroll
        for (int d = tid; d < D_IN; d += NTHREADS) {
            float sg = s1[d];
            int   hh = h1[d];
            atomicAdd(&z[hh].x, sg * x1r[d]);
            atomicAdd(&z[hh].y, sg * x2r[d]);
        }
    }
    __syncthreads();

    // --- forward FFT: radix-2 DIF, natural input -> bit-reversed output ---
    // stage s: half-length L = N/2^(s+1); twiddle index = j << s
    #pragma unroll
    for (int stage = 0; stage < LOG2N; ++stage) {
        const int L = N_FFT >> (1 + stage);
        #pragma unroll
        for (int q = tid; q < HALF_N; q += NTHREADS) {
            const int j = q & (L - 1);
            const int i = 2 * q - j;           // = block_base + j
            float2 a  = z[i];
            float2 c  = z[i + L];
            float2 w  = tw[j << stage];
            float2 sum = make_float2(a.x + c.x, a.y + c.y);
            float  dx = a.x - c.x;
            float  dy = a.y - c.y;
            z[i]     = sum;
            z[i + L] = make_float2(dx * w.x - dy * w.y,
                                   dx * w.y + dy * w.x);
        }
        __syncthreads();
    }

    // --- Hermitian split + pointwise product, in bit-reversed positions ---
    // Z holds FFT(y1 + i*y2). F1[k] = (Z[k]+conj(Z[N-k]))/2,
    // F2[k] = (Z[k]-conj(Z[N-k]))/(2i). P[k] = F1*F2, P[N-k] = conj(P[k]).
    #pragma unroll
    for (int k = tid; k < HALF_N; k += NTHREADS) {
        if (k == 0) {
            // DC bin: position brev(0)=0
            float2 z0 = z[0];
            z[0] = make_float2(z0.x * z0.y, 0.0f);
            // Nyquist bin: position brev(8192)=1
            float2 zn = z[1];
            z[1] = make_float2(zn.x * zn.y, 0.0f);
        } else {
            const int pa = (int)(__brev((unsigned)k)            >> (32 - LOG2N));
            const int pb = (int)(__brev((unsigned)(N_FFT - k))  >> (32 - LOG2N));
            float2 A  = z[pa];
            float2 Bv = z[pb];
            float f1r = 0.5f * (A.x + Bv.x);
            float f1i = 0.5f * (A.y - Bv.y);
            float f2r = 0.5f * (A.y + Bv.y);
            float f2i = 0.5f * (Bv.x - A.x);
            float pr  = f1r * f2r - f1i * f2i;
            float pi  = f1r * f2i + f1i * f2r;
            z[pa] = make_float2(pr,  pi);
            z[pb] = make_float2(pr, -pi);
        }
    }
    __syncthreads();

    // --- inverse FFT: radix-2 DIT, bit-reversed input -> natural output ---
    // conj twiddles; same index law (j << stage) with stage descending.
    #pragma unroll
    for (int stage = LOG2N - 1; stage >= 0; --stage) {
        const int L = N_FFT >> (1 + stage);
        #pragma unroll
        for (int q = tid; q < HALF_N; q += NTHREADS) {
            const int j = q & (L - 1);
            const int i = 2 * q - j;
            float2 w = tw[j << stage];
            w.y = -w.y;                        // conjugate for inverse
            float2 a = z[i];
            float2 c = z[i + L];
            float  bwx = c.x * w.x - c.y * w.y;
            float  bwy = c.x * w.y + c.y * w.x;
            z[i]     = make_float2(a.x + bwx, a.y + bwy);
            z[i + L] = make_float2(a.x - bwx, a.y - bwy);
        }
        __syncthreads();
    }

    // --- write real part, scaled by 1/N ---
    {
        const float invN = 1.0f / (float)N_FFT;
        float* outr = out + (size_t)b * N_FFT;
        #pragma unroll
        for (int i = tid; i < N_FFT; i += NTHREADS)
            outr[i] = z[i].x * invN;
    }
}

extern "C" void kernel_launch(void* const* d_in, const int* in_sizes, int n_in,
                              void* d_out, int out_size)
{
    const float* x1 = (const float*)d_in[0];
    const float* x2 = (const float*)d_in[1];
    const int*   h1 = (const int*)  d_in[2];
    const float* s1 = (const float*)d_in[3];
    float*       out = (float*)d_out;

    const int smem_bytes = (N_FFT + HALF_N) * (int)sizeof(float2);  // 196608
    cudaFuncSetAttribute(cbp_fft_kernel,
                         cudaFuncAttributeMaxDynamicSharedMemorySize,
                         smem_bytes);

    const int batch = 256;   // B from the problem spec (out_size / N_FFT)
    cbp_fft_kernel<<<batch, NTHREADS, smem_bytes>>>(x1, x2, h1, s1, out);
}

// round 2
// speedup vs baseline: 1.3508x; 1.3508x over previous
#include <cuda_runtime.h>
#include <cuda_bf16.h>

// CompactBilinearPooling: count-sketch of x1,x2 into O=16384 buckets, then
// circular convolution via FFT. One CTA per batch row; z = y1 + i*y2 packed
// in smem; radix-4 DIF forward (natural -> base4-digit-reversed), Hermitian
// split + pointwise product in digit-reversed positions, radix-4 DIT inverse
// (digit-reversed -> natural). No reordering passes.

#define N_FFT    16384
#define LOG2N    14
#define HALF_N   8192
#define QTR_N    4096
#define D_IN     4096
#define NTHREADS 1024
#define NPASSES  7                       // 4^7 = 16384
#define QPT      (QTR_N / NTHREADS)      // butterflies per thread per pass = 4

__device__ __forceinline__ float2 cadd(float2 a, float2 b) {
    return make_float2(a.x + b.x, a.y + b.y);
}
__device__ __forceinline__ float2 csub(float2 a, float2 b) {
    return make_float2(a.x - b.x, a.y - b.y);
}
__device__ __forceinline__ float2 cmul(float2 a, float2 b) {
    return make_float2(fmaf(a.x, b.x, -a.y * b.y),
                       fmaf(a.x, b.y,  a.y * b.x));
}
__device__ __forceinline__ float2 cconj(float2 a) {
    return make_float2(a.x, -a.y);
}

// base-4 digit reversal of a 14-bit index (7 digits):
// full bit-reverse, then swap adjacent bit pairs.
__device__ __forceinline__ int dr14(int k) {
    unsigned r = __brev((unsigned)k) >> (32 - LOG2N);
    return (int)(((r & 0x1555u) << 1) | ((r >> 1) & 0x1555u));
}

__global__ __launch_bounds__(NTHREADS, 1)
void cbp_fft4_kernel(const float* __restrict__ x1,
                     const float* __restrict__ x2,
                     const int*   __restrict__ h1,
                     const float* __restrict__ s1,
                     float*       __restrict__ out)
{
    extern __shared__ float2 smem[];
    float2* z  = smem;            // [N_FFT]  work array (y1 + i*y2)
    float2* tw = smem + N_FFT;    // [QTR_N]  twiddles exp(-2*pi*i*k/N), k<N/4

    const int tid = threadIdx.x;
    const int b   = blockIdx.x;

    // --- twiddle table ---
    #pragma unroll
    for (int k = tid; k < QTR_N; k += NTHREADS) {
        float s, c;
        sincospif(-2.0f * (float)k / (float)N_FFT, &s, &c);
        tw[k] = make_float2(c, s);
    }
    // --- zero the sketch accumulator ---
    #pragma unroll
    for (int i = tid; i < N_FFT; i += NTHREADS)
        z[i] = make_float2(0.0f, 0.0f);
    __syncthreads();

    // --- count-sketch scatter ---
    {
        const float* x1r = x1 + (size_t)b * D_IN;
        const float* x2r = x2 + (size_t)b * D_IN;
        #pragma unroll
        for (int d = tid; d < D_IN; d += NTHREADS) {
            float sg = s1[d];
            int   hh = h1[d];
            atomicAdd(&z[hh].x, sg * x1r[d]);
            atomicAdd(&z[hh].y, sg * x2r[d]);
        }
    }
    __syncthreads();

    // --- forward FFT: radix-4 DIF, natural -> base4-digit-reversed ---
    // pass s: L = N >> (2s+2); block = 4L; y_q stored at offset qL.
    #pragma unroll 1
    for (int pass = 0; pass < NPASSES; ++pass) {
        const int tshift = 2 * pass;
        const int L      = N_FFT >> (tshift + 2);
        #pragma unroll 1
        for (int it = 0; it < QPT; ++it) {
            const int q    = tid + it * NTHREADS;
            const int n    = q & (L - 1);
            const int base = 4 * q - 3 * n;       // blk*4L + n

            float2 a0 = z[base];
            float2 a1 = z[base + L];
            float2 a2 = z[base + 2 * L];
            float2 a3 = z[base + 3 * L];
            float2 w1 = tw[n << tshift];
            float2 w2 = cmul(w1, w1);
            float2 w3 = cmul(w2, w1);

            float2 t0 = cadd(a0, a2);
            float2 t1 = csub(a0, a2);
            float2 t2 = cadd(a1, a3);
            float2 t3 = csub(a1, a3);

            float2 y0 = cadd(t0, t2);
            float2 y2 = csub(t0, t2);
            float2 y1 = make_float2(t1.x + t3.y, t1.y - t3.x);  // t1 - i*t3
            float2 y3 = make_float2(t1.x - t3.y, t1.y + t3.x);  // t1 + i*t3

            z[base]         = y0;
            z[base + L]     = cmul(y1, w1);
            z[base + 2 * L] = cmul(y2, w2);
            z[base + 3 * L] = cmul(y3, w3);
        }
        __syncthreads();
    }

    // --- Hermitian split + pointwise product (digit-reversed positions) ---
    // Z = FFT(y1 + i*y2); F1[k]=(Z[k]+conj(Z[N-k]))/2, F2[k]=(Z[k]-conj(Z[N-k]))/(2i)
    // P[k]=F1*F2, P[N-k]=conj(P[k]).
    #pragma unroll 1
    for (int k = tid; k < HALF_N; k += NTHREADS) {
        if (k == 0) {
            float2 z0 = z[0];                      // DC at dr(0)=0
            z[0] = make_float2(z0.x * z0.y, 0.0f);
            float2 zn = z[2];                      // Nyquist at dr(8192)=2
            z[2] = make_float2(zn.x * zn.y, 0.0f);
        } else {
            const int pa = dr14(k);
            const int pb = dr14(N_FFT - k);
            float2 A  = z[pa];
            float2 Bv = z[pb];
            float f1r = 0.5f * (A.x + Bv.x);
            float f1i = 0.5f * (A.y - Bv.y);
            float f2r = 0.5f * (A.y + Bv.y);
            float f2i = 0.5f * (Bv.x - A.x);
            float pr  = f1r * f2r - f1i * f2i;
            float pi  = f1r * f2i + f1i * f2r;
            z[pa] = make_float2(pr,  pi);
            z[pb] = make_float2(pr, -pi);
        }
    }
    __syncthreads();

    // --- inverse FFT: radix-4 DIT, digit-reversed -> natural ---
    #pragma unroll 1
    for (int pass = NPASSES - 1; pass >= 0; --pass) {
        const int tshift = 2 * pass;
        const int L      = N_FFT >> (tshift + 2);
        #pragma unroll 1
        for (int it = 0; it < QPT; ++it) {
            const int q    = tid + it * NTHREADS;
            const int n    = q & (L - 1);
            const int base = 4 * q - 3 * n;

            float2 u0 = z[base];
            float2 u1 = z[base + L];
            float2 u2 = z[base + 2 * L];
            float2 u3 = z[base + 3 * L];
            float2 w1 = cconj(tw[n << tshift]);
            float2 w2 = cmul(w1, w1);
            float2 w3 = cmul(w2, w1);

            float2 t1 = cmul(u1, w1);
            float2 t2 = cmul(u2, w2);
            float2 t3 = cmul(u3, w3);

            float2 e0 = cadd(u0, t2);   // t0 + t2
            float2 e1 = csub(u0, t2);   // t0 - t2
            float2 e2 = cadd(t1, t3);   // t1 + t3
            float2 e3 = csub(t1, t3);   // t1 - t3

            z[base]         = cadd(e0, e2);                       // t0+t1+t2+t3
            z[base + L]     = make_float2(e1.x - e3.y, e1.y + e3.x); // e1 + i*e3
            z[base + 2 * L] = csub(e0, e2);
            z[base + 3 * L] = make_float2(e1.x + e3.y, e1.y - e3.x); // e1 - i*e3
        }
        __syncthreads();
    }

    // --- write real part / N ---
    {
        const float invN = 1.0f / (float)N_FFT;
        float* outr = out + (size_t)b * N_FFT;
        #pragma unroll
        for (int i = tid; i < N_FFT; i += NTHREADS)
            outr[i] = z[i].x * invN;
    }
}

extern "C" void kernel_launch(void* const* d_in, const int* in_sizes, int n_in,
                              void* d_out, int out_size)
{
    const float* x1 = (const float*)d_in[0];
    const float* x2 = (const float*)d_in[1];
    const int*   h1 = (const int*)  d_in[2];
    const float* s1 = (const float*)d_in[3];
    float*       out = (float*)d_out;

    const int smem_bytes = (N_FFT + QTR_N) * (int)sizeof(float2);  // 163840
    cudaFuncSetAttribute(cbp_fft4_kernel,
                         cudaFuncAttributeMaxDynamicSharedMemorySize,
                         smem_bytes);

    const int batch = out_size / N_FFT;   // 256
    cbp_fft4_kernel<<<batch, NTHREADS, smem_bytes>>>(x1, x2, h1, s1, out);
}

// round 3
// speedup vs baseline: 3.0088x; 2.2273x over previous
#include <cuda_runtime.h>
#include <cuda_bf16.h>

// CompactBilinearPooling: count-sketch into O=16384 buckets + circular conv
// via FFT. One CTA per batch row; z = y1 + i*y2 in padded smem.
// Forward: 3 radix-16 groups + 1 radix-4 pass (DIF, natural -> base4 digit
// reversed). Pointwise Hermitian product done per-position (conflict-free).
// Inverse mirrors, final group streams results directly to gmem.

#define N_FFT    16384
#define LOG2N    14
#define D_IN     4096
#define NTHREADS 1024
#define TW_N     4096
#define Z_SLOTS  17440   // slot(16383)=17437, rounded up

__device__ __forceinline__ int slotof(int i) { return i + (i >> 4) + (i >> 9); }

__device__ __forceinline__ float2 cadd(float2 a, float2 b) {
    return make_float2(a.x + b.x, a.y + b.y);
}
__device__ __forceinline__ float2 csub(float2 a, float2 b) {
    return make_float2(a.x - b.x, a.y - b.y);
}
__device__ __forceinline__ float2 cmul(float2 a, float2 b) {
    return make_float2(fmaf(a.x, b.x, -a.y * b.y),
                       fmaf(a.x, b.y,  a.y * b.x));
}
__device__ __forceinline__ float2 cconj(float2 a) {
    return make_float2(a.x, -a.y);
}

// base-4 digit reversal of 14-bit index (involution)
__device__ __forceinline__ int dr14(int k) {
    unsigned r = __brev((unsigned)k) >> (32 - LOG2N);
    return (int)(((r & 0x1555u) << 1) | ((r >> 1) & 0x1555u));
}

// radix-4 DIF butterfly over offsets {0,L,2L,3L}; post-twiddle by w^q
__device__ __forceinline__ void dif_bfly(float2& a0, float2& a1, float2& a2,
                                         float2& a3, float2 w1) {
    float2 w2 = cmul(w1, w1), w3 = cmul(w2, w1);
    float2 t0 = cadd(a0, a2), t1 = csub(a0, a2);
    float2 t2 = cadd(a1, a3), t3 = csub(a1, a3);
    float2 y0 = cadd(t0, t2);
    float2 y2 = csub(t0, t2);
    float2 y1 = make_float2(t1.x + t3.y, t1.y - t3.x);   // t1 - i*t3
    float2 y3 = make_float2(t1.x - t3.y, t1.y + t3.x);   // t1 + i*t3
    a0 = y0;
    a1 = cmul(y1, w1);
    a2 = cmul(y2, w2);
    a3 = cmul(y3, w3);
}

// radix-4 DIT butterfly (pre-twiddle by conj w^q); w1c already conjugated
__device__ __forceinline__ void dit_bfly(float2& a0, float2& a1, float2& a2,
                                         float2& a3, float2 w1c) {
    float2 w2 = cmul(w1c, w1c), w3 = cmul(w2, w1c);
    float2 t1 = cmul(a1, w1c), t2 = cmul(a2, w2), t3 = cmul(a3, w3);
    float2 e0 = cadd(a0, t2), e1 = csub(a0, t2);
    float2 e2 = cadd(t1, t3), e3 = csub(t1, t3);
    a0 = cadd(e0, e2);
    a1 = make_float2(e1.x - e3.y, e1.y + e3.x);          // e1 + i*e3
    a2 = csub(e0, e2);
    a3 = make_float2(e1.x + e3.y, e1.y - e3.x);          // e1 - i*e3
}

// combined radix-16 forward group = DIF pass p (L, tsh) then pass p+1.
// v[m] holds element ibase + m*(L/4); np = i & (L/4 - 1); step = L/4.
__device__ __forceinline__ void fwd16(float2* v, const float2* tw,
                                      int np, int step, int tsh) {
    #pragma unroll
    for (int m0 = 0; m0 < 4; ++m0)
        dif_bfly(v[m0], v[m0 + 4], v[m0 + 8], v[m0 + 12],
                 tw[(np + m0 * step) << tsh]);
    float2 w = tw[np << (tsh + 2)];
    #pragma unroll
    for (int q = 0; q < 4; ++q)
        dif_bfly(v[4 * q], v[4 * q + 1], v[4 * q + 2], v[4 * q + 3], w);
}

// combined radix-16 inverse group = DIT pass p+1 then pass p.
__device__ __forceinline__ void inv16(float2* v, const float2* tw,
                                      int np, int step, int tsh) {
    float2 w = cconj(tw[np << (tsh + 2)]);
    #pragma unroll
    for (int q = 0; q < 4; ++q)
        dit_bfly(v[4 * q], v[4 * q + 1], v[4 * q + 2], v[4 * q + 3], w);
    #pragma unroll
    for (int m0 = 0; m0 < 4; ++m0)
        dit_bfly(v[m0], v[m0 + 4], v[m0 + 8], v[m0 + 12],
                 cconj(tw[(np + m0 * step) << tsh]));
}

__global__ __launch_bounds__(NTHREADS, 1)
void cbp_fft16_kernel(const float* __restrict__ x1,
                      const float* __restrict__ x2,
                      const int*   __restrict__ h1,
                      const float* __restrict__ s1,
                      float*       __restrict__ out)
{
    extern __shared__ float2 smem[];
    float2* z  = smem;              // padded work array
    float2* tw = smem + Z_SLOTS;    // [TW_N] exp(-2*pi*i*k/N), k < N/4

    const int tid = threadIdx.x;
    const int b   = blockIdx.x;

    // twiddles + zero
    #pragma unroll
    for (int k = tid; k < TW_N; k += NTHREADS) {
        float s, c;
        sincospif(-(float)k * (1.0f / 8192.0f), &s, &c);
        tw[k] = make_float2(c, s);
    }
    #pragma unroll
    for (int i = tid; i < Z_SLOTS; i += NTHREADS)
        z[i] = make_float2(0.0f, 0.0f);
    __syncthreads();

    // count-sketch scatter: z.x <- y1, z.y <- y2
    {
        const float* x1r = x1 + (size_t)b * D_IN;
        const float* x2r = x2 + (size_t)b * D_IN;
        #pragma unroll
        for (int d = tid; d < D_IN; d += NTHREADS) {
            float sg = s1[d];
            int   sl = slotof(h1[d]);
            atomicAdd(&z[sl].x, sg * x1r[d]);
            atomicAdd(&z[sl].y, sg * x2r[d]);
        }
    }
    __syncthreads();

    float2 v[16];

    // ---------------- forward FFT ----------------
    // group A: passes p0,p1 (L=4096, stride 1024)
    {
        const int np = tid;
        #pragma unroll
        for (int m = 0; m < 16; ++m) v[m] = z[slotof(np + m * 1024)];
        fwd16(v, tw, np, 1024, 0);
        #pragma unroll
        for (int m = 0; m < 16; ++m) z[slotof(np + m * 1024)] = v[m];
    }
    __syncthreads();

    // group B: passes p2,p3 (L=256, stride 64)
    {
        const int np    = tid & 63;
        const int ibase = (tid >> 6) * 1024 + np;
        #pragma unroll
        for (int m = 0; m < 16; ++m) v[m] = z[slotof(ibase + m * 64)];
        fwd16(v, tw, np, 64, 4);
        #pragma unroll
        for (int m = 0; m < 16; ++m) z[slotof(ibase + m * 64)] = v[m];
    }
    __syncthreads();

    // group C: single radix-4 pass p4 (L=16, tsh=8)
    {
        int bases[4], ns[4];
        #pragma unroll
        for (int it = 0; it < 4; ++it) {
            int q   = tid + it * NTHREADS;
            ns[it]  = q & 15;
            bases[it] = 4 * q - 3 * ns[it];
        }
        #pragma unroll
        for (int it = 0; it < 4; ++it)
            #pragma unroll
            for (int c = 0; c < 4; ++c)
                v[4 * it + c] = z[slotof(bases[it] + 16 * c)];
        #pragma unroll
        for (int it = 0; it < 4; ++it)
            dif_bfly(v[4 * it], v[4 * it + 1], v[4 * it + 2], v[4 * it + 3],
                     tw[ns[it] << 8]);
        #pragma unroll
        for (int it = 0; it < 4; ++it)
            #pragma unroll
            for (int c = 0; c < 4; ++c)
                z[slotof(bases[it] + 16 * c)] = v[4 * it + c];
    }
    __syncthreads();

    // group D: passes p5,p6 (L=4, stride 1, contiguous 16 per thread)
    {
        const int ibase = 16 * tid;
        #pragma unroll
        for (int m = 0; m < 16; ++m) v[m] = z[slotof(ibase + m)];
        fwd16(v, tw, 0, 1, 10);
        #pragma unroll
        for (int m = 0; m < 16; ++m) z[slotof(ibase + m)] = v[m];
    }
    __syncthreads();

    // ---------- Hermitian split + pointwise product (per-position) ----------
    // Position j holds Z[k], k = dr14(j). Partner holds Z[(N-k) mod N].
    // F1 = (Z[k]+conj(Z[N-k]))/2, F2 = (Z[k]-conj(Z[N-k]))/(2i), P = F1*F2.
    // Formula is self-consistent for self-paired bins (DC, Nyquist).
    {
        float2 P[16];
        #pragma unroll
        for (int it = 0; it < 16; ++it) {
            int j  = tid + it * NTHREADS;
            int k  = dr14(j);
            int nk = (N_FFT - k) & (N_FFT - 1);
            int pj = dr14(nk);
            float2 A  = z[slotof(j)];
            float2 Bv = z[slotof(pj)];
            float f1r = 0.5f * (A.x + Bv.x);
            float f1i = 0.5f * (A.y - Bv.y);
            float f2r = 0.5f * (A.y + Bv.y);
            float f2i = 0.5f * (Bv.x - A.x);
            P[it] = make_float2(f1r * f2r - f1i * f2i,
                                f1r * f2i + f1i * f2r);
        }
        __syncthreads();
        #pragma unroll
        for (int it = 0; it < 16; ++it)
            z[slotof(tid + it * NTHREADS)] = P[it];
    }
    __syncthreads();

    // ---------------- inverse FFT ----------------
    // group D': passes p6,p5
    {
        const int ibase = 16 * tid;
        #pragma unroll
        for (int m = 0; m < 16; ++m) v[m] = z[slotof(ibase + m)];
        inv16(v, tw, 0, 1, 10);
        #pragma unroll
        for (int m = 0; m < 16; ++m) z[slotof(ibase + m)] = v[m];
    }
    __syncthreads();

    // group C': single radix-4 DIT pass p4
    {
        int bases[4], ns[4];
        #pragma unroll
        for (int it = 0; it < 4; ++it) {
            int q   = tid + it * NTHREADS;
            ns[it]  = q & 15;
            bases[it] = 4 * q - 3 * ns[it];
        }
        #pragma unroll
        for (int it = 0; it < 4; ++it)
            #pragma unroll
            for (int c = 0; c < 4; ++c)
                v[4 * it + c] = z[slotof(bases[it] + 16 * c)];
        #pragma unroll
        for (int it = 0; it < 4; ++it)
            dit_bfly(v[4 * it], v[4 * it + 1], v[4 * it + 2], v[4 * it + 3],
                     cconj(tw[ns[it] << 8]));
        #pragma unroll
        for (int it = 0; it < 4; ++it)
            #pragma unroll
            for (int c = 0; c < 4; ++c)
                z[slotof(bases[it] + 16 * c)] = v[4 * it + c];
    }
    __syncthreads();

    // group B': passes p3,p2
    {
        const int np    = tid & 63;
        const int ibase = (tid >> 6) * 1024 + np;
        #pragma unroll
        for (int m = 0; m < 16; ++m) v[m] = z[slotof(ibase + m * 64)];
        inv16(v, tw, np, 64, 4);
        #pragma unroll
        for (int m = 0; m < 16; ++m) z[slotof(ibase + m * 64)] = v[m];
    }
    __syncthreads();

    // group A': passes p1,p0 — fused gmem epilogue (real part / N)
    {
        const int np = tid;
        #pragma unroll
        for (int m = 0; m < 16; ++m) v[m] = z[slotof(np + m * 1024)];
        inv16(v, tw, np, 1024, 0);
        const float invN = 1.0f / (float)N_FFT;
        float* outr = out + (size_t)b * N_FFT;
        #pragma unroll
        for (int m = 0; m < 16; ++m)
            outr[np + m * 1024] = v[m].x * invN;
    }
}

extern "C" void kernel_launch(void* const* d_in, const int* in_sizes, int n_in,
                              void* d_out, int out_size)
{
    const float* x1 = (const float*)d_in[0];
    const float* x2 = (const float*)d_in[1];
    const int*   h1 = (const int*)  d_in[2];
    const float* s1 = (const float*)d_in[3];
    float*       out = (float*)d_out;

    const int smem_bytes = (Z_SLOTS + TW_N) * (int)sizeof(float2);  // 172288
    cudaFuncSetAttribute(cbp_fft16_kernel,
                         cudaFuncAttributeMaxDynamicSharedMemorySize,
                         smem_bytes);

    const int batch = out_size / N_FFT;   // 256
    cbp_fft16_kernel<<<batch, NTHREADS, smem_bytes>>>(x1, x2, h1, s1, out);
}

// round 4
// speedup vs baseline: 3.1434x; 1.0448x over previous
#include <cuda_runtime.h>
#include <cuda_bf16.h>

// CompactBilinearPooling: count-sketch into O=16384 buckets + circular conv
// via FFT. One CTA per batch row; z = y1 + i*y2 in padded smem.
// Forward: radix-16, radix-16, radix-4, radix-16 DIF groups (natural ->
// base4 digit reversed). The last forward group, the Hermitian pointwise
// product, and the first inverse group are fused in registers (only partner
// values touch smem). Inverse mirrors; final group streams to gmem.

#define N_FFT    16384
#define LOG2N    14
#define D_IN     4096
#define NTHREADS 1024
#define TW_N     4096
#define Z_SLOTS  17440   // slot(16383)=17437, rounded up

__device__ __forceinline__ int slotof(int i) { return i + (i >> 4) + (i >> 9); }

__device__ __forceinline__ float2 cadd(float2 a, float2 b) {
    return make_float2(a.x + b.x, a.y + b.y);
}
__device__ __forceinline__ float2 csub(float2 a, float2 b) {
    return make_float2(a.x - b.x, a.y - b.y);
}
__device__ __forceinline__ float2 cmul(float2 a, float2 b) {
    return make_float2(fmaf(a.x, b.x, -a.y * b.y),
                       fmaf(a.x, b.y,  a.y * b.x));
}
__device__ __forceinline__ float2 cconj(float2 a) {
    return make_float2(a.x, -a.y);
}

// base-4 digit reversal of 14-bit index (involution)
__device__ __forceinline__ int dr14(int k) {
    unsigned r = __brev((unsigned)k) >> (32 - LOG2N);
    return (int)(((r & 0x1555u) << 1) | ((r >> 1) & 0x1555u));
}

// radix-4 DIF butterfly over offsets {0,L,2L,3L}; post-twiddle by w^q
__device__ __forceinline__ void dif_bfly(float2& a0, float2& a1, float2& a2,
                                         float2& a3, float2 w1) {
    float2 w2 = cmul(w1, w1), w3 = cmul(w2, w1);
    float2 t0 = cadd(a0, a2), t1 = csub(a0, a2);
    float2 t2 = cadd(a1, a3), t3 = csub(a1, a3);
    float2 y0 = cadd(t0, t2);
    float2 y2 = csub(t0, t2);
    float2 y1 = make_float2(t1.x + t3.y, t1.y - t3.x);   // t1 - i*t3
    float2 y3 = make_float2(t1.x - t3.y, t1.y + t3.x);   // t1 + i*t3
    a0 = y0;
    a1 = cmul(y1, w1);
    a2 = cmul(y2, w2);
    a3 = cmul(y3, w3);
}

// radix-4 DIT butterfly (pre-twiddle by conj w^q); w1c already conjugated
__device__ __forceinline__ void dit_bfly(float2& a0, float2& a1, float2& a2,
                                         float2& a3, float2 w1c) {
    float2 w2 = cmul(w1c, w1c), w3 = cmul(w2, w1c);
    float2 t1 = cmul(a1, w1c), t2 = cmul(a2, w2), t3 = cmul(a3, w3);
    float2 e0 = cadd(a0, t2), e1 = csub(a0, t2);
    float2 e2 = cadd(t1, t3), e3 = csub(t1, t3);
    a0 = cadd(e0, e2);
    a1 = make_float2(e1.x - e3.y, e1.y + e3.x);          // e1 + i*e3
    a2 = csub(e0, e2);
    a3 = make_float2(e1.x + e3.y, e1.y - e3.x);          // e1 - i*e3
}

// combined radix-16 forward group = DIF pass p (L, tsh) then pass p+1.
// v[m] holds element ibase + m*(L/4); np = i & (L/4 - 1); step = L/4.
__device__ __forceinline__ void fwd16(float2* v, const float2* tw,
                                      int np, int step, int tsh) {
    #pragma unroll
    for (int m0 = 0; m0 < 4; ++m0)
        dif_bfly(v[m0], v[m0 + 4], v[m0 + 8], v[m0 + 12],
                 tw[(np + m0 * step) << tsh]);
    float2 w = tw[np << (tsh + 2)];
    #pragma unroll
    for (int q = 0; q < 4; ++q)
        dif_bfly(v[4 * q], v[4 * q + 1], v[4 * q + 2], v[4 * q + 3], w);
}

// combined radix-16 inverse group = DIT pass p+1 then pass p.
__device__ __forceinline__ void inv16(float2* v, const float2* tw,
                                      int np, int step, int tsh) {
    float2 w = cconj(tw[np << (tsh + 2)]);
    #pragma unroll
    for (int q = 0; q < 4; ++q)
        dit_bfly(v[4 * q], v[4 * q + 1], v[4 * q + 2], v[4 * q + 3], w);
    #pragma unroll
    for (int m0 = 0; m0 < 4; ++m0)
        dit_bfly(v[m0], v[m0 + 4], v[m0 + 8], v[m0 + 12],
                 cconj(tw[(np + m0 * step) << tsh]));
}

__global__ __launch_bounds__(NTHREADS, 1)
void cbp_fft16f_kernel(const float* __restrict__ x1,
                       const float* __restrict__ x2,
                       const int*   __restrict__ h1,
                       const float* __restrict__ s1,
                       float*       __restrict__ out)
{
    extern __shared__ float2 smem[];
    float2* z  = smem;              // padded work array
    float2* tw = smem + Z_SLOTS;    // [TW_N] exp(-2*pi*i*k/N), k < N/4

    const int tid = threadIdx.x;
    const int b   = blockIdx.x;

    // twiddles + zero
    #pragma unroll
    for (int k = tid; k < TW_N; k += NTHREADS) {
        float s, c;
        sincospif(-(float)k * (1.0f / 8192.0f), &s, &c);
        tw[k] = make_float2(c, s);
    }
    #pragma unroll
    for (int i = tid; i < Z_SLOTS; i += NTHREADS)
        z[i] = make_float2(0.0f, 0.0f);
    __syncthreads();

    // count-sketch scatter: z.x <- y1, z.y <- y2
    {
        const float* x1r = x1 + (size_t)b * D_IN;
        const float* x2r = x2 + (size_t)b * D_IN;
        #pragma unroll
        for (int d = tid; d < D_IN; d += NTHREADS) {
            float sg = s1[d];
            int   sl = slotof(h1[d]);
            atomicAdd(&z[sl].x, sg * x1r[d]);
            atomicAdd(&z[sl].y, sg * x2r[d]);
        }
    }
    __syncthreads();

    float2 v[16];

    // ---------------- forward FFT ----------------
    // group A: passes p0,p1 (L=4096, stride 1024)
    {
        const int np = tid;
        #pragma unroll
        for (int m = 0; m < 16; ++m) v[m] = z[slotof(np + m * 1024)];
        fwd16(v, tw, np, 1024, 0);
        #pragma unroll
        for (int m = 0; m < 16; ++m) z[slotof(np + m * 1024)] = v[m];
    }
    __syncthreads();

    // group B: passes p2,p3 (L=256, stride 64)
    {
        const int np    = tid & 63;
        const int ibase = (tid >> 6) * 1024 + np;
        #pragma unroll
        for (int m = 0; m < 16; ++m) v[m] = z[slotof(ibase + m * 64)];
        fwd16(v, tw, np, 64, 4);
        #pragma unroll
        for (int m = 0; m < 16; ++m) z[slotof(ibase + m * 64)] = v[m];
    }
    __syncthreads();

    // group C: single radix-4 pass p4 (L=16, tsh=8)
    {
        int bases[4], ns[4];
        #pragma unroll
        for (int it = 0; it < 4; ++it) {
            int q   = tid + it * NTHREADS;
            ns[it]  = q & 15;
            bases[it] = 4 * q - 3 * ns[it];
        }
        #pragma unroll
        for (int it = 0; it < 4; ++it)
            #pragma unroll
            for (int c = 0; c < 4; ++c)
                v[4 * it + c] = z[slotof(bases[it] + 16 * c)];
        #pragma unroll
        for (int it = 0; it < 4; ++it)
            dif_bfly(v[4 * it], v[4 * it + 1], v[4 * it + 2], v[4 * it + 3],
                     tw[ns[it] << 8]);
        #pragma unroll
        for (int it = 0; it < 4; ++it)
            #pragma unroll
            for (int c = 0; c < 4; ++c)
                z[slotof(bases[it] + 16 * c)] = v[4 * it + c];
    }
    __syncthreads();

    // ---- fused: group D (p5,p6) -> Hermitian pointwise -> group D' ----
    {
        const int ibase = 16 * tid;
        #pragma unroll
        for (int m = 0; m < 16; ++m) v[m] = z[slotof(ibase + m)];
        fwd16(v, tw, 0, 1, 10);
        // publish forward output so other threads can read their partners
        #pragma unroll
        for (int m = 0; m < 16; ++m) z[slotof(ibase + m)] = v[m];
        __syncthreads();

        // pointwise Hermitian product, own values already in v[m].
        // Position j holds Z[k], k = dr14(j); partner holds Z[(N-k) mod N].
        // F1=(Z[k]+conj(Z[N-k]))/2, F2=(Z[k]-conj(Z[N-k]))/(2i), P=F1*F2.
        // Formula is self-consistent for self-paired bins (DC, Nyquist).
        #pragma unroll
        for (int m = 0; m < 16; ++m) {
            int j  = ibase + m;
            int k  = dr14(j);
            int nk = (N_FFT - k) & (N_FFT - 1);
            int pj = dr14(nk);
            float2 A  = v[m];
            float2 Bv = z[slotof(pj)];
            float f1r = 0.5f * (A.x + Bv.x);
            float f1i = 0.5f * (A.y - Bv.y);
            float f2r = 0.5f * (A.y + Bv.y);
            float f2i = 0.5f * (Bv.x - A.x);
            v[m] = make_float2(f1r * f2r - f1i * f2i,
                               f1r * f2i + f1i * f2r);
        }
        // all partner reads must complete before anyone overwrites z
        __syncthreads();

        // inverse group D' (p6,p5) straight from registers
        inv16(v, tw, 0, 1, 10);
        #pragma unroll
        for (int m = 0; m < 16; ++m) z[slotof(ibase + m)] = v[m];
    }
    __syncthreads();

    // ---------------- inverse FFT (rest) ----------------
    // group C': single radix-4 DIT pass p4
    {
        int bases[4], ns[4];
        #pragma unroll
        for (int it = 0; it < 4; ++it) {
            int q   = tid + it * NTHREADS;
            ns[it]  = q & 15;
            bases[it] = 4 * q - 3 * ns[it];
        }
        #pragma unroll
        for (int it = 0; it < 4; ++it)
            #pragma unroll
            for (int c = 0; c < 4; ++c)
                v[4 * it + c] = z[slotof(bases[it] + 16 * c)];
        #pragma unroll
        for (int it = 0; it < 4; ++it)
            dit_bfly(v[4 * it], v[4 * it + 1], v[4 * it + 2], v[4 * it + 3],
                     cconj(tw[ns[it] << 8]));
        #pragma unroll
        for (int it = 0; it < 4; ++it)
            #pragma unroll
            for (int c = 0; c < 4; ++c)
                z[slotof(bases[it] + 16 * c)] = v[4 * it + c];
    }
    __syncthreads();

    // group B': passes p3,p2
    {
        const int np    = tid & 63;
        const int ibase = (tid >> 6) * 1024 + np;
        #pragma unroll
        for (int m = 0; m < 16; ++m) v[m] = z[slotof(ibase + m * 64)];
        inv16(v, tw, np, 64, 4);
        #pragma unroll
        for (int m = 0; m < 16; ++m) z[slotof(ibase + m * 64)] = v[m];
    }
    __syncthreads();

    // group A': passes p1,p0 — fused gmem epilogue (real part / N)
    {
        const int np = tid;
        #pragma unroll
        for (int m = 0; m < 16; ++m) v[m] = z[slotof(np + m * 1024)];
        inv16(v, tw, np, 1024, 0);
        const float invN = 1.0f / (float)N_FFT;
        float* outr = out + (size_t)b * N_FFT;
        #pragma unroll
        for (int m = 0; m < 16; ++m)
            outr[np + m * 1024] = v[m].x * invN;
    }
}

extern "C" void kernel_launch(void* const* d_in, const int* in_sizes, int n_in,
                              void* d_out, int out_size)
{
    const float* x1 = (const float*)d_in[0];
    const float* x2 = (const float*)d_in[1];
    const int*   h1 = (const int*)  d_in[2];
    const float* s1 = (const float*)d_in[3];
    float*       out = (float*)d_out;

    const int smem_bytes = (Z_SLOTS + TW_N) * (int)sizeof(float2);  // 172288
    cudaFuncSetAttribute(cbp_fft16f_kernel,
                         cudaFuncAttributeMaxDynamicSharedMemorySize,
                         smem_bytes);

    const int batch = out_size / N_FFT;   // 256
    cbp_fft16f_kernel<<<batch, NTHREADS, smem_bytes>>>(x1, x2, h1, s1, out);
}

// round 5
// speedup vs baseline: 3.3926x; 1.0793x over previous
#include <cuda_runtime.h>
#include <cuda_bf16.h>

// CompactBilinearPooling: count-sketch into O=16384 buckets + circular conv
// via FFT. One CTA per batch row, 512 threads, 32 elements per thread.
// Forward: radix-32 (stride 512), radix-32 (stride 16), radix-16 (contig)
// DIF groups. Pointwise Hermitian product fused with the last forward and
// first inverse group in registers. Inverse mirrors; epilogue streams to gmem.

#define N_FFT    16384
#define LOG2N    14
#define D_IN     4096
#define NTHREADS 512
#define TW_N     8192
#define Z_SLOTS  16896   // slot(16383)=16894, rounded up

__device__ __forceinline__ int slotof(int i) { return i + (i >> 5); }

__device__ __forceinline__ float2 cadd(float2 a, float2 b) {
    return make_float2(a.x + b.x, a.y + b.y);
}
__device__ __forceinline__ float2 csub(float2 a, float2 b) {
    return make_float2(a.x - b.x, a.y - b.y);
}
__device__ __forceinline__ float2 cmul(float2 a, float2 b) {
    return make_float2(fmaf(a.x, b.x, -a.y * b.y),
                       fmaf(a.x, b.y,  a.y * b.x));
}
__device__ __forceinline__ float2 cconj(float2 a) {
    return make_float2(a.x, -a.y);
}

// position <-> frequency involution for digit pattern [2,2,1,2,2,1,2,2]:
// 14-bit reverse, then swap adjacent bit pairs at {0,2,5,7,10,12}; bits 4,9 fixed.
__device__ __forceinline__ int rho(int j) {
    unsigned b = __brev((unsigned)j) >> (32 - LOG2N);
    return (int)(((b & 0x14A5u) << 1) | ((b >> 1) & 0x14A5u) | (b & 0x0210u));
}

// radix-4 DIF butterfly; post-twiddle by w^q
__device__ __forceinline__ void dif_bfly(float2& a0, float2& a1, float2& a2,
                                         float2& a3, float2 w1) {
    float2 w2 = cmul(w1, w1), w3 = cmul(w2, w1);
    float2 t0 = cadd(a0, a2), t1 = csub(a0, a2);
    float2 t2 = cadd(a1, a3), t3 = csub(a1, a3);
    float2 y0 = cadd(t0, t2);
    float2 y2 = csub(t0, t2);
    float2 y1 = make_float2(t1.x + t3.y, t1.y - t3.x);   // t1 - i*t3
    float2 y3 = make_float2(t1.x - t3.y, t1.y + t3.x);   // t1 + i*t3
    a0 = y0;
    a1 = cmul(y1, w1);
    a2 = cmul(y2, w2);
    a3 = cmul(y3, w3);
}

// radix-4 DIT butterfly (pre-twiddle by conj w^q); w1c already conjugated
__device__ __forceinline__ void dit_bfly(float2& a0, float2& a1, float2& a2,
                                         float2& a3, float2 w1c) {
    float2 w2 = cmul(w1c, w1c), w3 = cmul(w2, w1c);
    float2 t1 = cmul(a1, w1c), t2 = cmul(a2, w2), t3 = cmul(a3, w3);
    float2 e0 = cadd(a0, t2), e1 = csub(a0, t2);
    float2 e2 = cadd(t1, t3), e3 = csub(t1, t3);
    a0 = cadd(e0, e2);
    a1 = make_float2(e1.x - e3.y, e1.y + e3.x);          // e1 + i*e3
    a2 = csub(e0, e2);
    a3 = make_float2(e1.x + e3.y, e1.y - e3.x);          // e1 - i*e3
}

// radix-2 DIF: a'=a+b, b'=(a-b)w
__device__ __forceinline__ void dif2(float2& a, float2& b, float2 w) {
    float2 s = cadd(a, b), d = csub(a, b);
    a = s;
    b = cmul(d, w);
}
// radix-2 DIT: t=b*wc; a'=a+t, b'=a-t
__device__ __forceinline__ void dit2(float2& a, float2& b, float2 wc) {
    float2 t = cmul(b, wc);
    b = csub(a, t);
    a = cadd(a, t);
}

// 16-point DIF on 16 contiguous register elements (verified in R3/R4)
__device__ __forceinline__ void fwd16(float2* v, const float2* tw) {
    #pragma unroll
    for (int m0 = 0; m0 < 4; ++m0)
        dif_bfly(v[m0], v[m0 + 4], v[m0 + 8], v[m0 + 12], tw[m0 << 10]);
    float2 w = tw[0];
    #pragma unroll
    for (int q = 0; q < 4; ++q)
        dif_bfly(v[4 * q], v[4 * q + 1], v[4 * q + 2], v[4 * q + 3], w);
}
__device__ __forceinline__ void inv16(float2* v, const float2* tw) {
    float2 w = cconj(tw[0]);
    #pragma unroll
    for (int q = 0; q < 4; ++q)
        dit_bfly(v[4 * q], v[4 * q + 1], v[4 * q + 2], v[4 * q + 3], w);
    #pragma unroll
    for (int m0 = 0; m0 < 4; ++m0)
        dit_bfly(v[m0], v[m0 + 4], v[m0 + 8], v[m0 + 12],
                 cconj(tw[m0 << 10]));
}

__global__ __launch_bounds__(NTHREADS, 1)
void cbp_fft32_kernel(const float* __restrict__ x1,
                      const float* __restrict__ x2,
                      const int*   __restrict__ h1,
                      const float* __restrict__ s1,
                      float*       __restrict__ out)
{
    extern __shared__ float2 smem[];
    float2* z  = smem;              // padded work array
    float2* tw = smem + Z_SLOTS;    // [TW_N] exp(-2*pi*i*k/N), k < N/2

    const int tid = threadIdx.x;
    const int b   = blockIdx.x;

    // twiddles + zero
    #pragma unroll
    for (int k = tid; k < TW_N; k += NTHREADS) {
        float s, c;
        sincospif(-(float)k * (1.0f / 8192.0f), &s, &c);
        tw[k] = make_float2(c, s);
    }
    #pragma unroll
    for (int i = tid; i < Z_SLOTS; i += NTHREADS)
        z[i] = make_float2(0.0f, 0.0f);
    __syncthreads();

    // count-sketch scatter: z.x <- y1, z.y <- y2
    {
        const float* x1r = x1 + (size_t)b * D_IN;
        const float* x2r = x2 + (size_t)b * D_IN;
        #pragma unroll
        for (int d = tid; d < D_IN; d += NTHREADS) {
            float sg = s1[d];
            int   sl = slotof(h1[d]);
            atomicAdd(&z[sl].x, sg * x1r[d]);
            atomicAdd(&z[sl].y, sg * x2r[d]);
        }
    }
    __syncthreads();

    float2 v[32];

    // ============ forward group A: 5 bits, stride 512 ============
    // passes: radix-4 L=4096, radix-4 L=1024, radix-2 L=512
    {
        const int np = tid;
        #pragma unroll
        for (int m = 0; m < 32; ++m) v[m] = z[slotof(np + m * 512)];
        #pragma unroll
        for (int m0 = 0; m0 < 8; ++m0)
            dif_bfly(v[m0], v[m0 + 8], v[m0 + 16], v[m0 + 24],
                     tw[np + m0 * 512]);
        #pragma unroll
        for (int mb = 0; mb < 32; mb += 8)
            #pragma unroll
            for (int m0 = 0; m0 < 2; ++m0)
                dif_bfly(v[mb + m0], v[mb + m0 + 2], v[mb + m0 + 4],
                         v[mb + m0 + 6], tw[(np + m0 * 512) << 2]);
        {
            float2 w = tw[np << 4];
            #pragma unroll
            for (int m = 0; m < 32; m += 2) dif2(v[m], v[m + 1], w);
        }
        #pragma unroll
        for (int m = 0; m < 32; ++m) z[slotof(np + m * 512)] = v[m];
    }
    __syncthreads();

    // ============ forward group B: 5 bits, stride 16 within 512-blocks ====
    // passes: radix-4 L=128, radix-4 L=32, radix-2 L=16
    {
        const int lane = tid & 15;
        const int base = (tid >> 4) * 512 + lane;
        #pragma unroll
        for (int m = 0; m < 32; ++m) v[m] = z[slotof(base + m * 16)];
        #pragma unroll
        for (int m0 = 0; m0 < 8; ++m0)
            dif_bfly(v[m0], v[m0 + 8], v[m0 + 16], v[m0 + 24],
                     tw[(lane + m0 * 16) << 5]);
        #pragma unroll
        for (int mb = 0; mb < 32; mb += 8)
            #pragma unroll
            for (int m0 = 0; m0 < 2; ++m0)
                dif_bfly(v[mb + m0], v[mb + m0 + 2], v[mb + m0 + 4],
                         v[mb + m0 + 6], tw[(lane + m0 * 16) << 7]);
        {
            float2 w = tw[lane << 9];
            #pragma unroll
            for (int m = 0; m < 32; m += 2) dif2(v[m], v[m + 1], w);
        }
        #pragma unroll
        for (int m = 0; m < 32; ++m) z[slotof(base + m * 16)] = v[m];
    }
    __syncthreads();

    // ==== fused: group C (two 16-pt FFTs) -> pointwise -> group C' ====
    {
        const int ibase = tid * 32;
        #pragma unroll
        for (int m = 0; m < 32; ++m) v[m] = z[slotof(ibase + m)];
        fwd16(v, tw);
        fwd16(v + 16, tw);
        // publish forward output so other threads can read partners
        #pragma unroll
        for (int m = 0; m < 32; ++m) z[slotof(ibase + m)] = v[m];
        __syncthreads();

        // Hermitian split + pointwise product, own values already in v[m].
        // Position j holds Z[k], k = rho(j); partner holds Z[(N-k) mod N].
        // F1=(Z[k]+conj(Z[N-k]))/2, F2=(Z[k]-conj(Z[N-k]))/(2i), P=F1*F2.
        // Self-consistent for self-paired bins (DC, Nyquist).
        #pragma unroll
        for (int m = 0; m < 32; ++m) {
            int j  = ibase + m;
            int k  = rho(j);
            int nk = (N_FFT - k) & (N_FFT - 1);
            int pj = rho(nk);
            float2 A  = v[m];
            float2 Bv = z[slotof(pj)];
            float f1r = 0.5f * (A.x + Bv.x);
            float f1i = 0.5f * (A.y - Bv.y);
            float f2r = 0.5f * (A.y + Bv.y);
            float f2i = 0.5f * (Bv.x - A.x);
            v[m] = make_float2(f1r * f2r - f1i * f2i,
                               f1r * f2i + f1i * f2r);
        }
        __syncthreads();   // partner reads done before anyone overwrites z

        inv16(v, tw);
        inv16(v + 16, tw);
        #pragma unroll
        for (int m = 0; m < 32; ++m) z[slotof(ibase + m)] = v[m];
    }
    __syncthreads();

    // ============ inverse group B' ============
    {
        const int lane = tid & 15;
        const int base = (tid >> 4) * 512 + lane;
        #pragma unroll
        for (int m = 0; m < 32; ++m) v[m] = z[slotof(base + m * 16)];
        {
            float2 wc = cconj(tw[lane << 9]);
            #pragma unroll
            for (int m = 0; m < 32; m += 2) dit2(v[m], v[m + 1], wc);
        }
        #pragma unroll
        for (int mb = 0; mb < 32; mb += 8)
            #pragma unroll
            for (int m0 = 0; m0 < 2; ++m0)
                dit_bfly(v[mb + m0], v[mb + m0 + 2], v[mb + m0 + 4],
                         v[mb + m0 + 6], cconj(tw[(lane + m0 * 16) << 7]));
        #pragma unroll
        for (int m0 = 0; m0 < 8; ++m0)
            dit_bfly(v[m0], v[m0 + 8], v[m0 + 16], v[m0 + 24],
                     cconj(tw[(lane + m0 * 16) << 5]));
        #pragma unroll
        for (int m = 0; m < 32; ++m) z[slotof(base + m * 16)] = v[m];
    }
    __syncthreads();

    // ============ inverse group A' + fused gmem epilogue ============
    {
        const int np = tid;
        #pragma unroll
        for (int m = 0; m < 32; ++m) v[m] = z[slotof(np + m * 512)];
        {
            float2 wc = cconj(tw[np << 4]);
            #pragma unroll
            for (int m = 0; m < 32; m += 2) dit2(v[m], v[m + 1], wc);
        }
        #pragma unroll
        for (int mb = 0; mb < 32; mb += 8)
            #pragma unroll
            for (int m0 = 0; m0 < 2; ++m0)
                dit_bfly(v[mb + m0], v[mb + m0 + 2], v[mb + m0 + 4],
                         v[mb + m0 + 6], cconj(tw[(np + m0 * 512) << 2]));
        #pragma unroll
        for (int m0 = 0; m0 < 8; ++m0)
            dit_bfly(v[m0], v[m0 + 8], v[m0 + 16], v[m0 + 24],
                     cconj(tw[np + m0 * 512]));

        const float invN = 1.0f / (float)N_FFT;
        float* outr = out + (size_t)b * N_FFT;
        #pragma unroll
        for (int m = 0; m < 32; ++m)
            outr[np + m * 512] = v[m].x * invN;
    }
}

extern "C" void kernel_launch(void* const* d_in, const int* in_sizes, int n_in,
                              void* d_out, int out_size)
{
    const float* x1 = (const float*)d_in[0];
    const float* x2 = (const float*)d_in[1];
    const int*   h1 = (const int*)  d_in[2];
    const float* s1 = (const float*)d_in[3];
    float*       out = (float*)d_out;

    const int smem_bytes = (Z_SLOTS + TW_N) * (int)sizeof(float2);  // 200704
    cudaFuncSetAttribute(cbp_fft32_kernel,
                         cudaFuncAttributeMaxDynamicSharedMemorySize,
                         smem_bytes);

    const int batch = out_size / N_FFT;   // 256
    cbp_fft32_kernel<<<batch, NTHREADS, smem_bytes>>>(x1, x2, h1, s1, out);
}

// round 6
// speedup vs baseline: 3.6846x; 1.0861x over previous
#include <cuda_runtime.h>
#include <cuda_bf16.h>

// CompactBilinearPooling: count-sketch into O=16384 buckets + circular conv
// via FFT. One CTA per batch row, 512 threads, 32 elements per thread.
// Forward: radix-32 (stride 512), radix-32 (stride 16), radix-16 (contig)
// DIF groups. Pointwise Hermitian product fused with the last forward and
// first inverse group in registers; partner indices computed in closed form
// (contiguous partner blocks). B<->C exchanges are warp-local (syncwarp).
// Packed f32x2 add/sub for butterfly adds. Inverse mirrors; epilogue -> gmem.

#define N_FFT    16384
#define LOG2N    14
#define D_IN     4096
#define NTHREADS 512
#define TW_N     4096
#define Z_SLOTS  16896   // slot(16383)=16894, rounded up

__device__ __forceinline__ int slotof(int i) { return i + (i >> 5); }

// packed fp32x2 add/sub (sm_103a)
__device__ __forceinline__ float2 cadd(float2 a, float2 b) {
    float2 r;
    asm("{\n\t.reg .b64 ra, rb, rc;\n\t"
        "mov.b64 ra, {%2,%3};\n\t"
        "mov.b64 rb, {%4,%5};\n\t"
        "add.rn.f32x2 rc, ra, rb;\n\t"
        "mov.b64 {%0,%1}, rc;\n\t}"
        : "=f"(r.x), "=f"(r.y)
        : "f"(a.x), "f"(a.y), "f"(b.x), "f"(b.y));
    return r;
}
__device__ __forceinline__ float2 csub(float2 a, float2 b) {
    float2 r;
    asm("{\n\t.reg .b64 ra, rb, rc;\n\t"
        "mov.b64 ra, {%2,%3};\n\t"
        "mov.b64 rb, {%4,%5};\n\t"
        "sub.rn.f32x2 rc, ra, rb;\n\t"
        "mov.b64 {%0,%1}, rc;\n\t}"
        : "=f"(r.x), "=f"(r.y)
        : "f"(a.x), "f"(a.y), "f"(b.x), "f"(b.y));
    return r;
}
__device__ __forceinline__ float2 cmul(float2 a, float2 b) {
    return make_float2(fmaf(a.x, b.x, -a.y * b.y),
                       fmaf(a.x, b.y,  a.y * b.x));
}
__device__ __forceinline__ float2 cconj(float2 a) {
    return make_float2(a.x, -a.y);
}

// twiddle fetch for indices in [0, 8192): table holds k < 4096;
// w^(4096+r) = -i * w^r = (s, -c)
__device__ __forceinline__ float2 twr2(const float2* tw, int idx) {
    float2 t = tw[idx & (TW_N - 1)];
    return (idx & TW_N) ? make_float2(t.y, -t.x) : t;
}

// position <-> frequency involution for digit pattern [2,2,1,2,2,1,2,2]:
// 14-bit reverse, then swap adjacent bit pairs at {0,2,5,7,10,12}; bits 4,9 fixed.
__device__ __forceinline__ int rho(int j) {
    unsigned b = __brev((unsigned)j) >> (32 - LOG2N);
    return (int)(((b & 0x14A5u) << 1) | ((b >> 1) & 0x14A5u) | (b & 0x0210u));
}

// radix-4 DIF butterfly; post-twiddle by w^q
__device__ __forceinline__ void dif_bfly(float2& a0, float2& a1, float2& a2,
                                         float2& a3, float2 w1) {
    float2 w2 = cmul(w1, w1), w3 = cmul(w2, w1);
    float2 t0 = cadd(a0, a2), t1 = csub(a0, a2);
    float2 t2 = cadd(a1, a3), t3 = csub(a1, a3);
    float2 y0 = cadd(t0, t2);
    float2 y2 = csub(t0, t2);
    float2 y1 = make_float2(t1.x + t3.y, t1.y - t3.x);   // t1 - i*t3
    float2 y3 = make_float2(t1.x - t3.y, t1.y + t3.x);   // t1 + i*t3
    a0 = y0;
    a1 = cmul(y1, w1);
    a2 = cmul(y2, w2);
    a3 = cmul(y3, w3);
}

// radix-4 DIT butterfly (pre-twiddle by conj w^q); w1c already conjugated
__device__ __forceinline__ void dit_bfly(float2& a0, float2& a1, float2& a2,
                                         float2& a3, float2 w1c) {
    float2 w2 = cmul(w1c, w1c), w3 = cmul(w2, w1c);
    float2 t1 = cmul(a1, w1c), t2 = cmul(a2, w2), t3 = cmul(a3, w3);
    float2 e0 = cadd(a0, t2), e1 = csub(a0, t2);
    float2 e2 = cadd(t1, t3), e3 = csub(t1, t3);
    a0 = cadd(e0, e2);
    a1 = make_float2(e1.x - e3.y, e1.y + e3.x);          // e1 + i*e3
    a2 = csub(e0, e2);
    a3 = make_float2(e1.x + e3.y, e1.y - e3.x);          // e1 - i*e3
}

// radix-2 DIF: a'=a+b, b'=(a-b)w
__device__ __forceinline__ void dif2(float2& a, float2& b, float2 w) {
    float2 s = cadd(a, b), d = csub(a, b);
    a = s;
    b = cmul(d, w);
}
// radix-2 DIT: t=b*wc; a'=a+t, b'=a-t
__device__ __forceinline__ void dit2(float2& a, float2& b, float2 wc) {
    float2 t = cmul(b, wc);
    b = csub(a, t);
    a = cadd(a, t);
}

// 16-point DIF on 16 contiguous register elements
__device__ __forceinline__ void fwd16(float2* v, const float2* tw) {
    #pragma unroll
    for (int m0 = 0; m0 < 4; ++m0)
        dif_bfly(v[m0], v[m0 + 4], v[m0 + 8], v[m0 + 12], tw[m0 << 10]);
    float2 w = tw[0];
    #pragma unroll
    for (int q = 0; q < 4; ++q)
        dif_bfly(v[4 * q], v[4 * q + 1], v[4 * q + 2], v[4 * q + 3], w);
}
__device__ __forceinline__ void inv16(float2* v, const float2* tw) {
    float2 w = cconj(tw[0]);
    #pragma unroll
    for (int q = 0; q < 4; ++q)
        dit_bfly(v[4 * q], v[4 * q + 1], v[4 * q + 2], v[4 * q + 3], w);
    #pragma unroll
    for (int m0 = 0; m0 < 4; ++m0)
        dit_bfly(v[m0], v[m0 + 4], v[m0 + 8], v[m0 + 12],
                 cconj(tw[m0 << 10]));
}

__global__ __launch_bounds__(NTHREADS, 1)
void cbp_fft32b_kernel(const float* __restrict__ x1,
                       const float* __restrict__ x2,
                       const int*   __restrict__ h1,
                       const float* __restrict__ s1,
                       float*       __restrict__ out)
{
    extern __shared__ float2 smem[];
    float2* z  = smem;              // padded work array
    float2* tw = smem + Z_SLOTS;    // [TW_N] exp(-2*pi*i*k/N), k < N/4

    const int tid = threadIdx.x;
    const int b   = blockIdx.x;

    // twiddles + zero
    #pragma unroll
    for (int k = tid; k < TW_N; k += NTHREADS) {
        float s, c;
        sincospif(-(float)k * (1.0f / 8192.0f), &s, &c);
        tw[k] = make_float2(c, s);
    }
    #pragma unroll
    for (int i = tid; i < Z_SLOTS; i += NTHREADS)
        z[i] = make_float2(0.0f, 0.0f);
    __syncthreads();

    // count-sketch scatter: z.x <- y1, z.y <- y2
    {
        const float* x1r = x1 + (size_t)b * D_IN;
        const float* x2r = x2 + (size_t)b * D_IN;
        #pragma unroll
        for (int d = tid; d < D_IN; d += NTHREADS) {
            float sg = s1[d];
            int   sl = slotof(h1[d]);
            atomicAdd(&z[sl].x, sg * x1r[d]);
            atomicAdd(&z[sl].y, sg * x2r[d]);
        }
    }
    __syncthreads();

    float2 v[32];

    // ============ forward group A: 5 bits, stride 512 ============
    // passes: radix-4 L=4096, radix-4 L=1024, radix-2 L=512
    {
        const int np = tid;
        #pragma unroll
        for (int m = 0; m < 32; ++m) v[m] = z[slotof(np + m * 512)];
        #pragma unroll
        for (int m0 = 0; m0 < 8; ++m0)
            dif_bfly(v[m0], v[m0 + 8], v[m0 + 16], v[m0 + 24],
                     tw[np + m0 * 512]);
        #pragma unroll
        for (int mb = 0; mb < 32; mb += 8)
            #pragma unroll
            for (int m0 = 0; m0 < 2; ++m0)
                dif_bfly(v[mb + m0], v[mb + m0 + 2], v[mb + m0 + 4],
                         v[mb + m0 + 6], tw[(np + m0 * 512) << 2]);
        {
            float2 w = twr2(tw, np << 4);
            #pragma unroll
            for (int m = 0; m < 32; m += 2) dif2(v[m], v[m + 1], w);
        }
        #pragma unroll
        for (int m = 0; m < 32; ++m) z[slotof(np + m * 512)] = v[m];
    }
    __syncthreads();

    // ============ forward group B: 5 bits, stride 16 within 512-blocks ====
    // passes: radix-4 L=128, radix-4 L=32, radix-2 L=16
    {
        const int lane = tid & 15;
        const int base = (tid >> 4) * 512 + lane;
        #pragma unroll
        for (int m = 0; m < 32; ++m) v[m] = z[slotof(base + m * 16)];
        #pragma unroll
        for (int m0 = 0; m0 < 8; ++m0)
            dif_bfly(v[m0], v[m0 + 8], v[m0 + 16], v[m0 + 24],
                     tw[(lane + m0 * 16) << 5]);
        #pragma unroll
        for (int mb = 0; mb < 32; mb += 8)
            #pragma unroll
            for (int m0 = 0; m0 < 2; ++m0)
                dif_bfly(v[mb + m0], v[mb + m0 + 2], v[mb + m0 + 4],
                         v[mb + m0 + 6], tw[(lane + m0 * 16) << 7]);
        {
            float2 w = twr2(tw, lane << 9);
            #pragma unroll
            for (int m = 0; m < 32; m += 2) dif2(v[m], v[m + 1], w);
        }
        #pragma unroll
        for (int m = 0; m < 32; ++m) z[slotof(base + m * 16)] = v[m];
    }
    // exchange with group C is confined to 16 threads of the same warp
    __syncwarp();

    // ==== fused: group C (two 16-pt FFTs) -> pointwise -> group C' ====
    {
        const int ibase = tid * 32;
        #pragma unroll
        for (int m = 0; m < 32; ++m) v[m] = z[slotof(ibase + m)];
        fwd16(v, tw);
        fwd16(v + 16, tw);
        // publish forward output so other threads can read partners
        #pragma unroll
        for (int m = 0; m < 32; ++m) z[slotof(ibase + m)] = v[m];
        __syncthreads();

        // Hermitian split + pointwise product.
        // Position j holds Z[k], k = rho(j); partner holds Z[(N-k) mod N].
        // Since rho is a bit permutation and own block is 32-aligned:
        // for khi = rho(ibase) != 0, partner(ibase+m) = pbase + (31-m),
        // pbase = rho(512 - khi) (contiguous, 32-aligned).
        if (tid != 0) {
            const int khi = rho(ibase);
            const int pb  = rho(512 - khi);
            const int ps  = pb + (pb >> 5);     // slot base; pb low 5 bits = 0
            #pragma unroll
            for (int m = 0; m < 32; ++m) {
                float2 A  = v[m];
                float2 Bv = z[ps + 31 - m];
                float f1r = 0.5f * (A.x + Bv.x);
                float f1i = 0.5f * (A.y - Bv.y);
                float f2r = 0.5f * (A.y + Bv.y);
                float f2i = 0.5f * (Bv.x - A.x);
                v[m] = make_float2(f1r * f2r - f1i * f2i,
                                   f1r * f2i + f1i * f2r);
            }
        } else {
            // general path (self-paired DC handled by the same formula)
            #pragma unroll
            for (int m = 0; m < 32; ++m) {
                int k  = rho(m);
                int nk = (N_FFT - k) & (N_FFT - 1);
                int pj = rho(nk);
                float2 A  = v[m];
                float2 Bv = z[slotof(pj)];
                float f1r = 0.5f * (A.x + Bv.x);
                float f1i = 0.5f * (A.y - Bv.y);
                float f2r = 0.5f * (A.y + Bv.y);
                float f2i = 0.5f * (Bv.x - A.x);
                v[m] = make_float2(f1r * f2r - f1i * f2i,
                                   f1r * f2i + f1i * f2r);
            }
        }
        __syncthreads();   // all partner reads done before anyone overwrites z

        inv16(v, tw);
        inv16(v + 16, tw);
        #pragma unroll
        for (int m = 0; m < 32; ++m) z[slotof(ibase + m)] = v[m];
    }
    // exchange with group B' is warp-local
    __syncwarp();

    // ============ inverse group B' ============
    {
        const int lane = tid & 15;
        const int base = (tid >> 4) * 512 + lane;
        #pragma unroll
        for (int m = 0; m < 32; ++m) v[m] = z[slotof(base + m * 16)];
        {
            float2 wc = cconj(twr2(tw, lane << 9));
            #pragma unroll
            for (int m = 0; m < 32; m += 2) dit2(v[m], v[m + 1], wc);
        }
        #pragma unroll
        for (int mb = 0; mb < 32; mb += 8)
            #pragma unroll
            for (int m0 = 0; m0 < 2; ++m0)
                dit_bfly(v[mb + m0], v[mb + m0 + 2], v[mb + m0 + 4],
                         v[mb + m0 + 6], cconj(tw[(lane + m0 * 16) << 7]));
        #pragma unroll
        for (int m0 = 0; m0 < 8; ++m0)
            dit_bfly(v[m0], v[m0 + 8], v[m0 + 16], v[m0 + 24],
                     cconj(tw[(lane + m0 * 16) << 5]));
        #pragma unroll
        for (int m = 0; m < 32; ++m) z[slotof(base + m * 16)] = v[m];
    }
    __syncthreads();

    // ============ inverse group A' + fused gmem epilogue ============
    {
        const int np = tid;
        #pragma unroll
        for (int m = 0; m < 32; ++m) v[m] = z[slotof(np + m * 512)];
        {
            float2 wc = cconj(twr2(tw, np << 4));
            #pragma unroll
            for (int m = 0; m < 32; m += 2) dit2(v[m], v[m + 1], wc);
        }
        #pragma unroll
        for (int mb = 0; mb < 32; mb += 8)
            #pragma unroll
            for (int m0 = 0; m0 < 2; ++m0)
                dit_bfly(v[mb + m0], v[mb + m0 + 2], v[mb + m0 + 4],
                         v[mb + m0 + 6], cconj(tw[(np + m0 * 512) << 2]));
        #pragma unroll
        for (int m0 = 0; m0 < 8; ++m0)
            dit_bfly(v[m0], v[m0 + 8], v[m0 + 16], v[m0 + 24],
                     cconj(tw[np + m0 * 512]));

        const float invN = 1.0f / (float)N_FFT;
        float* outr = out + (size_t)b * N_FFT;
        #pragma unroll
        for (int m = 0; m < 32; ++m)
            outr[np + m * 512] = v[m].x * invN;
    }
}

extern "C" void kernel_launch(void* const* d_in, const int* in_sizes, int n_in,
                              void* d_out, int out_size)
{
    const float* x1 = (const float*)d_in[0];
    const float* x2 = (const float*)d_in[1];
    const int*   h1 = (const int*)  d_in[2];
    const float* s1 = (const float*)d_in[3];
    float*       out = (float*)d_out;

    const int smem_bytes = (Z_SLOTS + TW_N) * (int)sizeof(float2);  // 167936
    cudaFuncSetAttribute(cbp_fft32b_kernel,
                         cudaFuncAttributeMaxDynamicSharedMemorySize,
                         smem_bytes);

    const int batch = out_size / N_FFT;   // 256
    cbp_fft32b_kernel<<<batch, NTHREADS, smem_bytes>>>(x1, x2, h1, s1, out);
}

// round 7
// speedup vs baseline: 3.8476x; 1.0442x over previous
#include <cuda_runtime.h>
#include <cuda_bf16.h>

// CompactBilinearPooling: count-sketch into O=16384 buckets + circular conv
// via FFT. One CTA per batch row, 512 threads, 32 elements per thread.
// Forward: radix-32 (stride 512), radix-32 (stride 16), radix-16 (contig)
// DIF groups. Pointwise Hermitian product fused with the last forward and
// first inverse group in registers; partner indices in closed form.
// Contiguous phases use 128-bit smem ops (pad = 2 slots per 32 elements so
// 32-blocks are 16B-aligned). B<->C exchanges are warp-local (syncwarp).

#define N_FFT    16384
#define LOG2N    14
#define D_IN     4096
#define NTHREADS 512
#define TW_N     4096
#define Z_SLOTS  17408   // slot(16383)=16383+2*511=17405, rounded to /4

__device__ __forceinline__ int slotof(int i) { return i + 2 * (i >> 5); }

// packed fp32x2 add/sub (sm_103a)
__device__ __forceinline__ float2 cadd(float2 a, float2 b) {
    float2 r;
    asm("{\n\t.reg .b64 ra, rb, rc;\n\t"
        "mov.b64 ra, {%2,%3};\n\t"
        "mov.b64 rb, {%4,%5};\n\t"
        "add.rn.f32x2 rc, ra, rb;\n\t"
        "mov.b64 {%0,%1}, rc;\n\t}"
        : "=f"(r.x), "=f"(r.y)
        : "f"(a.x), "f"(a.y), "f"(b.x), "f"(b.y));
    return r;
}
__device__ __forceinline__ float2 csub(float2 a, float2 b) {
    float2 r;
    asm("{\n\t.reg .b64 ra, rb, rc;\n\t"
        "mov.b64 ra, {%2,%3};\n\t"
        "mov.b64 rb, {%4,%5};\n\t"
        "sub.rn.f32x2 rc, ra, rb;\n\t"
        "mov.b64 {%0,%1}, rc;\n\t}"
        : "=f"(r.x), "=f"(r.y)
        : "f"(a.x), "f"(a.y), "f"(b.x), "f"(b.y));
    return r;
}
__device__ __forceinline__ float2 cmul(float2 a, float2 b) {
    return make_float2(fmaf(a.x, b.x, -a.y * b.y),
                       fmaf(a.x, b.y,  a.y * b.x));
}
__device__ __forceinline__ float2 cconj(float2 a) {
    return make_float2(a.x, -a.y);
}

// twiddle fetch for indices in [0, 8192): table holds k < 4096;
// w^(4096+r) = -i * w^r = (s, -c)
__device__ __forceinline__ float2 twr2(const float2* tw, int idx) {
    float2 t = tw[idx & (TW_N - 1)];
    return (idx & TW_N) ? make_float2(t.y, -t.x) : t;
}

// position <-> frequency involution for digit pattern [2,2,1,2,2,1,2,2]:
// 14-bit reverse, then swap adjacent bit pairs at {0,2,5,7,10,12}; bits 4,9 fixed.
__device__ __forceinline__ int rho(int j) {
    unsigned b = __brev((unsigned)j) >> (32 - LOG2N);
    return (int)(((b & 0x14A5u) << 1) | ((b >> 1) & 0x14A5u) | (b & 0x0210u));
}

// radix-4 DIF butterfly; post-twiddle by w^q
__device__ __forceinline__ void dif_bfly(float2& a0, float2& a1, float2& a2,
                                         float2& a3, float2 w1) {
    float2 w2 = cmul(w1, w1), w3 = cmul(w2, w1);
    float2 t0 = cadd(a0, a2), t1 = csub(a0, a2);
    float2 t2 = cadd(a1, a3), t3 = csub(a1, a3);
    float2 y0 = cadd(t0, t2);
    float2 y2 = csub(t0, t2);
    float2 y1 = make_float2(t1.x + t3.y, t1.y - t3.x);   // t1 - i*t3
    float2 y3 = make_float2(t1.x - t3.y, t1.y + t3.x);   // t1 + i*t3
    a0 = y0;
    a1 = cmul(y1, w1);
    a2 = cmul(y2, w2);
    a3 = cmul(y3, w3);
}

// radix-4 DIT butterfly (pre-twiddle by conj w^q); w1c already conjugated
__device__ __forceinline__ void dit_bfly(float2& a0, float2& a1, float2& a2,
                                         float2& a3, float2 w1c) {
    float2 w2 = cmul(w1c, w1c), w3 = cmul(w2, w1c);
    float2 t1 = cmul(a1, w1c), t2 = cmul(a2, w2), t3 = cmul(a3, w3);
    float2 e0 = cadd(a0, t2), e1 = csub(a0, t2);
    float2 e2 = cadd(t1, t3), e3 = csub(t1, t3);
    a0 = cadd(e0, e2);
    a1 = make_float2(e1.x - e3.y, e1.y + e3.x);          // e1 + i*e3
    a2 = csub(e0, e2);
    a3 = make_float2(e1.x + e3.y, e1.y - e3.x);          // e1 - i*e3
}

// radix-2 DIF: a'=a+b, b'=(a-b)w
__device__ __forceinline__ void dif2(float2& a, float2& b, float2 w) {
    float2 s = cadd(a, b), d = csub(a, b);
    a = s;
    b = cmul(d, w);
}
// radix-2 DIT: t=b*wc; a'=a+t, b'=a-t
__device__ __forceinline__ void dit2(float2& a, float2& b, float2 wc) {
    float2 t = cmul(b, wc);
    b = csub(a, t);
    a = cadd(a, t);
}

// 16-point DIF on 16 contiguous register elements
__device__ __forceinline__ void fwd16(float2* v, const float2* tw) {
    #pragma unroll
    for (int m0 = 0; m0 < 4; ++m0)
        dif_bfly(v[m0], v[m0 + 4], v[m0 + 8], v[m0 + 12], tw[m0 << 10]);
    float2 w = tw[0];
    #pragma unroll
    for (int q = 0; q < 4; ++q)
        dif_bfly(v[4 * q], v[4 * q + 1], v[4 * q + 2], v[4 * q + 3], w);
}
__device__ __forceinline__ void inv16(float2* v, const float2* tw) {
    float2 w = cconj(tw[0]);
    #pragma unroll
    for (int q = 0; q < 4; ++q)
        dit_bfly(v[4 * q], v[4 * q + 1], v[4 * q + 2], v[4 * q + 3], w);
    #pragma unroll
    for (int m0 = 0; m0 < 4; ++m0)
        dit_bfly(v[m0], v[m0 + 4], v[m0 + 8], v[m0 + 12],
                 cconj(tw[m0 << 10]));
}

__global__ __launch_bounds__(NTHREADS, 1)
void cbp_fft32c_kernel(const float* __restrict__ x1,
                       const float* __restrict__ x2,
                       const int*   __restrict__ h1,
                       const float* __restrict__ s1,
                       float*       __restrict__ out)
{
    extern __shared__ float2 smem[];
    float2* z  = smem;              // padded work array
    float2* tw = smem + Z_SLOTS;    // [TW_N] exp(-2*pi*i*k/N), k < N/4
    float4* z4 = reinterpret_cast<float4*>(smem);

    const int tid = threadIdx.x;
    const int b   = blockIdx.x;

    // --- twiddles: 4 sincospif + 4 derived via w^(k+2048) = w^k * e^{-i pi/4}
    {
        const float2 c8 = make_float2(0.70710678118654752f,
                                      -0.70710678118654752f);
        #pragma unroll
        for (int it = 0; it < 4; ++it) {
            int k = tid + it * NTHREADS;     // k < 2048
            float s, c;
            sincospif(-(float)k * (1.0f / 8192.0f), &s, &c);
            float2 w = make_float2(c, s);
            tw[k]        = w;
            tw[k + 2048] = cmul(w, c8);
        }
    }
    // --- zero the padded work array (float4 stores) ---
    #pragma unroll
    for (int i = tid; i < Z_SLOTS / 2; i += NTHREADS)
        z4[i] = make_float4(0.0f, 0.0f, 0.0f, 0.0f);
    __syncthreads();

    // --- count-sketch scatter (vectorized input loads) ---
    {
        const float4* x1v = reinterpret_cast<const float4*>(x1 + (size_t)b * D_IN);
        const float4* x2v = reinterpret_cast<const float4*>(x2 + (size_t)b * D_IN);
        const int4*   h1v = reinterpret_cast<const int4*>(h1);
        const float4* s1v = reinterpret_cast<const float4*>(s1);
        #pragma unroll
        for (int it = 0; it < 2; ++it) {
            int idx = tid + it * NTHREADS;   // float4 index, < 1024
            float4 a1 = x1v[idx];
            float4 a2 = x2v[idx];
            int4   hh = h1v[idx];
            float4 ss = s1v[idx];
            int s0 = slotof(hh.x), s1i = slotof(hh.y);
            int s2 = slotof(hh.z), s3 = slotof(hh.w);
            atomicAdd(&z[s0].x,  ss.x * a1.x);
            atomicAdd(&z[s0].y,  ss.x * a2.x);
            atomicAdd(&z[s1i].x, ss.y * a1.y);
            atomicAdd(&z[s1i].y, ss.y * a2.y);
            atomicAdd(&z[s2].x,  ss.z * a1.z);
            atomicAdd(&z[s2].y,  ss.z * a2.z);
            atomicAdd(&z[s3].x,  ss.w * a1.w);
            atomicAdd(&z[s3].y,  ss.w * a2.w);
        }
    }
    __syncthreads();

    float2 v[32];

    // ============ forward group A: 5 bits, stride 512 ============
    // passes: radix-4 L=4096, radix-4 L=1024, radix-2 L=512
    {
        const int np = tid;
        #pragma unroll
        for (int m = 0; m < 32; ++m) v[m] = z[slotof(np + m * 512)];
        #pragma unroll
        for (int m0 = 0; m0 < 8; ++m0)
            dif_bfly(v[m0], v[m0 + 8], v[m0 + 16], v[m0 + 24],
                     tw[np + m0 * 512]);
        #pragma unroll
        for (int mb = 0; mb < 32; mb += 8)
            #pragma unroll
            for (int m0 = 0; m0 < 2; ++m0)
                dif_bfly(v[mb + m0], v[mb + m0 + 2], v[mb + m0 + 4],
                         v[mb + m0 + 6], tw[(np + m0 * 512) << 2]);
        {
            float2 w = twr2(tw, np << 4);
            #pragma unroll
            for (int m = 0; m < 32; m += 2) dif2(v[m], v[m + 1], w);
        }
        #pragma unroll
        for (int m = 0; m < 32; ++m) z[slotof(np + m * 512)] = v[m];
    }
    __syncthreads();

    // ============ forward group B: 5 bits, stride 16 within 512-blocks ====
    // passes: radix-4 L=128, radix-4 L=32, radix-2 L=16
    {
        const int lane = tid & 15;
        const int base = (tid >> 4) * 512 + lane;
        #pragma unroll
        for (int m = 0; m < 32; ++m) v[m] = z[slotof(base + m * 16)];
        #pragma unroll
        for (int m0 = 0; m0 < 8; ++m0)
            dif_bfly(v[m0], v[m0 + 8], v[m0 + 16], v[m0 + 24],
                     tw[(lane + m0 * 16) << 5]);
        #pragma unroll
        for (int mb = 0; mb < 32; mb += 8)
            #pragma unroll
            for (int m0 = 0; m0 < 2; ++m0)
                dif_bfly(v[mb + m0], v[mb + m0 + 2], v[mb + m0 + 4],
                         v[mb + m0 + 6], tw[(lane + m0 * 16) << 7]);
        {
            float2 w = twr2(tw, lane << 9);
            #pragma unroll
            for (int m = 0; m < 32; m += 2) dif2(v[m], v[m + 1], w);
        }
        #pragma unroll
        for (int m = 0; m < 32; ++m) z[slotof(base + m * 16)] = v[m];
    }
    // exchange with group C is confined to 16 threads of the same warp
    __syncwarp();

    // ==== fused: group C (two 16-pt FFTs) -> pointwise -> group C' ====
    // Own 32-block starts at float2-slot 34*tid (16B-aligned): float4 ops.
    {
        const int f4base = 17 * tid;     // float4 index of own block
        #pragma unroll
        for (int j = 0; j < 16; ++j) {
            float4 q = z4[f4base + j];
            v[2 * j]     = make_float2(q.x, q.y);
            v[2 * j + 1] = make_float2(q.z, q.w);
        }
        fwd16(v, tw);
        fwd16(v + 16, tw);
        // publish forward output so other threads can read partners
        #pragma unroll
        for (int j = 0; j < 16; ++j)
            z4[f4base + j] = make_float4(v[2 * j].x, v[2 * j].y,
                                         v[2 * j + 1].x, v[2 * j + 1].y);
        __syncthreads();

        // Hermitian split + pointwise product.
        // Position j holds Z[k], k = rho(j); partner holds Z[(N-k) mod N].
        // For khi = rho(32*tid) != 0: partner(ibase+m) = pbase + (31-m),
        // pbase = rho(512 - khi) (contiguous, 32-aligned).
        if (tid != 0) {
            const int khi = rho(32 * tid);
            const int pb  = rho(512 - khi);        // 32-aligned block base
            const int pf4 = 17 * (pb >> 5);        // float4 index of partner
            #pragma unroll
            for (int jj = 0; jj < 16; ++jj) {
                float4 pq = z4[pf4 + 15 - jj];
                // own element 2jj pairs with partner element 31-2jj (high),
                // own element 2jj+1 pairs with 30-2jj (low)
                float2 A0 = v[2 * jj];
                float2 B0 = make_float2(pq.z, pq.w);
                float2 A1 = v[2 * jj + 1];
                float2 B1 = make_float2(pq.x, pq.y);
                {
                    float f1r = 0.5f * (A0.x + B0.x);
                    float f1i = 0.5f * (A0.y - B0.y);
                    float f2r = 0.5f * (A0.y + B0.y);
                    float f2i = 0.5f * (B0.x - A0.x);
                    v[2 * jj] = make_float2(f1r * f2r - f1i * f2i,
                                            f1r * f2i + f1i * f2r);
                }
                {
                    float f1r = 0.5f * (A1.x + B1.x);
                    float f1i = 0.5f * (A1.y - B1.y);
                    float f2r = 0.5f * (A1.y + B1.y);
                    float f2i = 0.5f * (B1.x - A1.x);
                    v[2 * jj + 1] = make_float2(f1r * f2r - f1i * f2i,
                                                f1r * f2i + f1i * f2r);
                }
            }
        } else {
            // block 0 partners itself; general per-element path
            #pragma unroll
            for (int m = 0; m < 32; ++m) {
                int k  = rho(m);
                int nk = (N_FFT - k) & (N_FFT - 1);
                int pj = rho(nk);
                float2 A  = v[m];
                float2 Bv = z[slotof(pj)];
                float f1r = 0.5f * (A.x + Bv.x);
                float f1i = 0.5f * (A.y - Bv.y);
                float f2r = 0.5f * (A.y + Bv.y);
                float f2i = 0.5f * (Bv.x - A.x);
                v[m] = make_float2(f1r * f2r - f1i * f2i,
                                   f1r * f2i + f1i * f2r);
            }
        }
        __syncthreads();   // all partner reads done before anyone overwrites z

        inv16(v, tw);
        inv16(v + 16, tw);
        #pragma unroll
        for (int j = 0; j < 16; ++j)
            z4[f4base + j] = make_float4(v[2 * j].x, v[2 * j].y,
                                         v[2 * j + 1].x, v[2 * j + 1].y);
    }
    // exchange with group B' is warp-local
    __syncwarp();

    // ============ inverse group B' ============
    {
        const int lane = tid & 15;
        const int base = (tid >> 4) * 512 + lane;
        #pragma unroll
        for (int m = 0; m < 32; ++m) v[m] = z[slotof(base + m * 16)];
        {
            float2 wc = cconj(twr2(tw, lane << 9));
            #pragma unroll
            for (int m = 0; m < 32; m += 2) dit2(v[m], v[m + 1], wc);
        }
        #pragma unroll
        for (int mb = 0; mb < 32; mb += 8)
            #pragma unroll
            for (int m0 = 0; m0 < 2; ++m0)
                dit_bfly(v[mb + m0], v[mb + m0 + 2], v[mb + m0 + 4],
                         v[mb + m0 + 6], cconj(tw[(lane + m0 * 16) << 7]));
        #pragma unroll
        for (int m0 = 0; m0 < 8; ++m0)
            dit_bfly(v[m0], v[m0 + 8], v[m0 + 16], v[m0 + 24],
                     cconj(tw[(lane + m0 * 16) << 5]));
        #pragma unroll
        for (int m = 0; m < 32; ++m) z[slotof(base + m * 16)] = v[m];
    }
    __syncthreads();

    // ============ inverse group A' + fused gmem epilogue ============
    {
        const int np = tid;
        #pragma unroll
        for (int m = 0; m < 32; ++m) v[m] = z[slotof(np + m * 512)];
        {
            float2 wc = cconj(twr2(tw, np << 4));
            #pragma unroll
            for (int m = 0; m < 32; m += 2) dit2(v[m], v[m + 1], wc);
        }
        #pragma unroll
        for (int mb = 0; mb < 32; mb += 8)
            #pragma unroll
            for (int m0 = 0; m0 < 2; ++m0)
                dit_bfly(v[mb + m0], v[mb + m0 + 2], v[mb + m0 + 4],
                         v[mb + m0 + 6], cconj(tw[(np + m0 * 512) << 2]));
        #pragma unroll
        for (int m0 = 0; m0 < 8; ++m0)
            dit_bfly(v[m0], v[m0 + 8], v[m0 + 16], v[m0 + 24],
                     cconj(tw[np + m0 * 512]));

        const float invN = 1.0f / (float)N_FFT;
        float* outr = out + (size_t)b * N_FFT;
        #pragma unroll
        for (int m = 0; m < 32; ++m)
            outr[np + m * 512] = v[m].x * invN;
    }
}

extern "C" void kernel_launch(void* const* d_in, const int* in_sizes, int n_in,
                              void* d_out, int out_size)
{
    const float* x1 = (const float*)d_in[0];
    const float* x2 = (const float*)d_in[1];
    const int*   h1 = (const int*)  d_in[2];
    const float* s1 = (const float*)d_in[3];
    float*       out = (float*)d_out;

    const int smem_bytes = (Z_SLOTS + TW_N) * (int)sizeof(float2);  // 172032
    cudaFuncSetAttribute(cbp_fft32c_kernel,
                         cudaFuncAttributeMaxDynamicSharedMemorySize,
                         smem_bytes);

    const int batch = out_size / N_FFT;   // 256
    cbp_fft32c_kernel<<<batch, NTHREADS, smem_bytes>>>(x1, x2, h1, s1, out);
}

// round 8
// speedup vs baseline: 3.9847x; 1.0356x over previous
#include <cuda_runtime.h>
#include <cuda_bf16.h>

// CompactBilinearPooling: count-sketch into O=16384 buckets + circular conv
// via FFT. One CTA per batch row, 512 threads, 32 elements per thread.
// Forward: radix-32 (stride 512), radix-32 (stride 16), radix-16 (contig)
// DIF groups. Pointwise Hermitian product fused with the last forward and
// first inverse group in registers; partner indices in closed form.
// 16-pt FFT layers use hardcoded-immediate twiddles and twiddle-free
// butterflies where w==1. Inputs prefetched before prologue; 1/N folded
// into the pointwise constants.

#define N_FFT    16384
#define LOG2N    14
#define D_IN     4096
#define NTHREADS 512
#define TW_N     4096
#define Z_SLOTS  17408   // slot(16383)=16383+2*511=17405, rounded to /4

__device__ __forceinline__ int slotof(int i) { return i + 2 * (i >> 5); }

// packed fp32x2 add/sub (sm_103a)
__device__ __forceinline__ float2 cadd(float2 a, float2 b) {
    float2 r;
    asm("{\n\t.reg .b64 ra, rb, rc;\n\t"
        "mov.b64 ra, {%2,%3};\n\t"
        "mov.b64 rb, {%4,%5};\n\t"
        "add.rn.f32x2 rc, ra, rb;\n\t"
        "mov.b64 {%0,%1}, rc;\n\t}"
        : "=f"(r.x), "=f"(r.y)
        : "f"(a.x), "f"(a.y), "f"(b.x), "f"(b.y));
    return r;
}
__device__ __forceinline__ float2 csub(float2 a, float2 b) {
    float2 r;
    asm("{\n\t.reg .b64 ra, rb, rc;\n\t"
        "mov.b64 ra, {%2,%3};\n\t"
        "mov.b64 rb, {%4,%5};\n\t"
        "sub.rn.f32x2 rc, ra, rb;\n\t"
        "mov.b64 {%0,%1}, rc;\n\t}"
        : "=f"(r.x), "=f"(r.y)
        : "f"(a.x), "f"(a.y), "f"(b.x), "f"(b.y));
    return r;
}
__device__ __forceinline__ float2 cmul(float2 a, float2 b) {
    return make_float2(fmaf(a.x, b.x, -a.y * b.y),
                       fmaf(a.x, b.y,  a.y * b.x));
}
__device__ __forceinline__ float2 cconj(float2 a) {
    return make_float2(a.x, -a.y);
}

// twiddle fetch for indices in [0, 8192): table holds k < 4096;
// w^(4096+r) = -i * w^r = (s, -c)
__device__ __forceinline__ float2 twr2(const float2* tw, int idx) {
    float2 t = tw[idx & (TW_N - 1)];
    return (idx & TW_N) ? make_float2(t.y, -t.x) : t;
}

// position <-> frequency involution for digit pattern [2,2,1,2,2,1,2,2]:
// 14-bit reverse, then swap adjacent bit pairs at {0,2,5,7,10,12}; bits 4,9 fixed.
__device__ __forceinline__ int rho(int j) {
    unsigned b = __brev((unsigned)j) >> (32 - LOG2N);
    return (int)(((b & 0x14A5u) << 1) | ((b >> 1) & 0x14A5u) | (b & 0x0210u));
}

// radix-4 DIF butterfly; post-twiddle by w^q (w1 loaded from table)
__device__ __forceinline__ void dif_bfly(float2& a0, float2& a1, float2& a2,
                                         float2& a3, float2 w1) {
    float2 w2 = cmul(w1, w1), w3 = cmul(w2, w1);
    float2 t0 = cadd(a0, a2), t1 = csub(a0, a2);
    float2 t2 = cadd(a1, a3), t3 = csub(a1, a3);
    float2 y0 = cadd(t0, t2);
    float2 y2 = csub(t0, t2);
    float2 y1 = make_float2(t1.x + t3.y, t1.y - t3.x);   // t1 - i*t3
    float2 y3 = make_float2(t1.x - t3.y, t1.y + t3.x);   // t1 + i*t3
    a0 = y0;
    a1 = cmul(y1, w1);
    a2 = cmul(y2, w2);
    a3 = cmul(y3, w3);
}
// radix-4 DIF butterfly with all three twiddles given (immediates)
__device__ __forceinline__ void dif_w(float2& a0, float2& a1, float2& a2,
                                      float2& a3, float2 w1, float2 w2,
                                      float2 w3) {
    float2 t0 = cadd(a0, a2), t1 = csub(a0, a2);
    float2 t2 = cadd(a1, a3), t3 = csub(a1, a3);
    float2 y0 = cadd(t0, t2);
    float2 y2 = csub(t0, t2);
    float2 y1 = make_float2(t1.x + t3.y, t1.y - t3.x);
    float2 y3 = make_float2(t1.x - t3.y, t1.y + t3.x);
    a0 = y0;
    a1 = cmul(y1, w1);
    a2 = cmul(y2, w2);
    a3 = cmul(y3, w3);
}
// radix-4 DIF butterfly, w == 1 (twiddle-free; bit-exact vs cmul by (1,0))
__device__ __forceinline__ void dif_nt(float2& a0, float2& a1, float2& a2,
                                       float2& a3) {
    float2 t0 = cadd(a0, a2), t1 = csub(a0, a2);
    float2 t2 = cadd(a1, a3), t3 = csub(a1, a3);
    a0 = cadd(t0, t2);
    a2 = csub(t0, t2);
    a1 = make_float2(t1.x + t3.y, t1.y - t3.x);
    a3 = make_float2(t1.x - t3.y, t1.y + t3.x);
}

// radix-4 DIT butterfly (pre-twiddle by conj w^q); w1c already conjugated
__device__ __forceinline__ void dit_bfly(float2& a0, float2& a1, float2& a2,
                                         float2& a3, float2 w1c) {
    float2 w2 = cmul(w1c, w1c), w3 = cmul(w2, w1c);
    float2 t1 = cmul(a1, w1c), t2 = cmul(a2, w2), t3 = cmul(a3, w3);
    float2 e0 = cadd(a0, t2), e1 = csub(a0, t2);
    float2 e2 = cadd(t1, t3), e3 = csub(t1, t3);
    a0 = cadd(e0, e2);
    a1 = make_float2(e1.x - e3.y, e1.y + e3.x);          // e1 + i*e3
    a2 = csub(e0, e2);
    a3 = make_float2(e1.x + e3.y, e1.y - e3.x);          // e1 - i*e3
}
// radix-4 DIT with all three conj twiddles given (immediates)
__device__ __forceinline__ void dit_w(float2& a0, float2& a1, float2& a2,
                                      float2& a3, float2 w1c, float2 w2c,
                                      float2 w3c) {
    float2 t1 = cmul(a1, w1c), t2 = cmul(a2, w2c), t3 = cmul(a3, w3c);
    float2 e0 = cadd(a0, t2), e1 = csub(a0, t2);
    float2 e2 = cadd(t1, t3), e3 = csub(t1, t3);
    a0 = cadd(e0, e2);
    a1 = make_float2(e1.x - e3.y, e1.y + e3.x);
    a2 = csub(e0, e2);
    a3 = make_float2(e1.x + e3.y, e1.y - e3.x);
}
// radix-4 DIT, w == 1
__device__ __forceinline__ void dit_nt(float2& a0, float2& a1, float2& a2,
                                       float2& a3) {
    float2 e0 = cadd(a0, a2), e1 = csub(a0, a2);
    float2 e2 = cadd(a1, a3), e3 = csub(a1, a3);
    a0 = cadd(e0, e2);
    a1 = make_float2(e1.x - e3.y, e1.y + e3.x);
    a2 = csub(e0, e2);
    a3 = make_float2(e1.x + e3.y, e1.y - e3.x);
}

// radix-2 DIF: a'=a+b, b'=(a-b)w
__device__ __forceinline__ void dif2(float2& a, float2& b, float2 w) {
    float2 s = cadd(a, b), d = csub(a, b);
    a = s;
    b = cmul(d, w);
}
// radix-2 DIT: t=b*wc; a'=a+t, b'=a-t
__device__ __forceinline__ void dit2(float2& a, float2& b, float2 wc) {
    float2 t = cmul(b, wc);
    b = csub(a, t);
    a = cadd(a, t);
}

// 16th-root twiddle constants: W = exp(-2*pi*i/16)
#define C16A 0.92387953251128674f   // cos(pi/8)
#define S16A 0.38268343236508978f   // sin(pi/8)
#define RS2  0.70710678118654752f   // 1/sqrt(2)

// 16-point DIF on 16 contiguous register elements; second layer twiddles
// are all 1 (final DIF stage), first-layer twiddles are immediates.
__device__ __forceinline__ void fwd16(float2* v) {
    dif_nt(v[0], v[4], v[8], v[12]);
    dif_w(v[1], v[5], v[9], v[13],
          make_float2( C16A, -S16A), make_float2( RS2, -RS2),
          make_float2( S16A, -C16A));
    dif_w(v[2], v[6], v[10], v[14],
          make_float2( RS2, -RS2), make_float2(0.0f, -1.0f),
          make_float2(-RS2, -RS2));
    dif_w(v[3], v[7], v[11], v[15],
          make_float2( S16A, -C16A), make_float2(-RS2, -RS2),
          make_float2(-C16A,  S16A));
    #pragma unroll
    for (int q = 0; q < 4; ++q)
        dif_nt(v[4 * q], v[4 * q + 1], v[4 * q + 2], v[4 * q + 3]);
}
__device__ __forceinline__ void inv16(float2* v) {
    #pragma unroll
    for (int q = 0; q < 4; ++q)
        dit_nt(v[4 * q], v[4 * q + 1], v[4 * q + 2], v[4 * q + 3]);
    dit_nt(v[0], v[4], v[8], v[12]);
    dit_w(v[1], v[5], v[9], v[13],
          make_float2( C16A,  S16A), make_float2( RS2,  RS2),
          make_float2( S16A,  C16A));
    dit_w(v[2], v[6], v[10], v[14],
          make_float2( RS2,  RS2), make_float2(0.0f, 1.0f),
          make_float2(-RS2,  RS2));
    dit_w(v[3], v[7], v[11], v[15],
          make_float2( S16A,  C16A), make_float2(-RS2,  RS2),
          make_float2(-C16A, -S16A));
}

__global__ __launch_bounds__(NTHREADS, 1)
void cbp_fft32d_kernel(const float* __restrict__ x1,
                       const float* __restrict__ x2,
                       const int*   __restrict__ h1,
                       const float* __restrict__ s1,
                       float*       __restrict__ out)
{
    extern __shared__ float2 smem[];
    float2* z  = smem;              // padded work array
    float2* tw = smem + Z_SLOTS;    // [TW_N] exp(-2*pi*i*k/N), k < N/4
    float4* z4 = reinterpret_cast<float4*>(smem);

    const int tid = threadIdx.x;
    const int b   = blockIdx.x;

    // --- prefetch inputs (hide DRAM latency behind twiddle gen + zeroing) ---
    float4 pa1[2], pa2[2], pss[2];
    int4   phh[2];
    {
        const float4* x1v = reinterpret_cast<const float4*>(x1 + (size_t)b * D_IN);
        const float4* x2v = reinterpret_cast<const float4*>(x2 + (size_t)b * D_IN);
        const int4*   h1v = reinterpret_cast<const int4*>(h1);
        const float4* s1v = reinterpret_cast<const float4*>(s1);
        #pragma unroll
        for (int it = 0; it < 2; ++it) {
            int idx = tid + it * NTHREADS;
            pa1[it] = x1v[idx];
            pa2[it] = x2v[idx];
            phh[it] = h1v[idx];
            pss[it] = s1v[idx];
        }
    }

    // --- twiddles: 4 sincospif + 4 derived via w^(k+2048) = w^k * e^{-i pi/4}
    {
        const float2 c8 = make_float2(RS2, -RS2);
        #pragma unroll
        for (int it = 0; it < 4; ++it) {
            int k = tid + it * NTHREADS;     // k < 2048
            float s, c;
            sincospif(-(float)k * (1.0f / 8192.0f), &s, &c);
            float2 w = make_float2(c, s);
            tw[k]        = w;
            tw[k + 2048] = cmul(w, c8);
        }
    }
    // --- zero the padded work array (float4 stores) ---
    #pragma unroll
    for (int i = tid; i < Z_SLOTS / 2; i += NTHREADS)
        z4[i] = make_float4(0.0f, 0.0f, 0.0f, 0.0f);
    __syncthreads();

    // --- count-sketch scatter from prefetched registers ---
    #pragma unroll
    for (int it = 0; it < 2; ++it) {
        float4 a1 = pa1[it];
        float4 a2 = pa2[it];
        int4   hh = phh[it];
        float4 ss = pss[it];
        int s0 = slotof(hh.x), s1i = slotof(hh.y);
        int s2 = slotof(hh.z), s3 = slotof(hh.w);
        atomicAdd(&z[s0].x,  ss.x * a1.x);
        atomicAdd(&z[s0].y,  ss.x * a2.x);
        atomicAdd(&z[s1i].x, ss.y * a1.y);
        atomicAdd(&z[s1i].y, ss.y * a2.y);
        atomicAdd(&z[s2].x,  ss.z * a1.z);
        atomicAdd(&z[s2].y,  ss.z * a2.z);
        atomicAdd(&z[s3].x,  ss.w * a1.w);
        atomicAdd(&z[s3].y,  ss.w * a2.w);
    }
    __syncthreads();

    float2 v[32];

    // ============ forward group A: 5 bits, stride 512 ============
    // passes: radix-4 L=4096, radix-4 L=1024, radix-2 L=512
    {
        const int np = tid;
        #pragma unroll
        for (int m = 0; m < 32; ++m) v[m] = z[slotof(np + m * 512)];
        #pragma unroll
        for (int m0 = 0; m0 < 8; ++m0)
            dif_bfly(v[m0], v[m0 + 8], v[m0 + 16], v[m0 + 24],
                     tw[np + m0 * 512]);
        #pragma unroll
        for (int mb = 0; mb < 32; mb += 8)
            #pragma unroll
            for (int m0 = 0; m0 < 2; ++m0)
                dif_bfly(v[mb + m0], v[mb + m0 + 2], v[mb + m0 + 4],
                         v[mb + m0 + 6], tw[(np + m0 * 512) << 2]);
        {
            float2 w = twr2(tw, np << 4);
            #pragma unroll
            for (int m = 0; m < 32; m += 2) dif2(v[m], v[m + 1], w);
        }
        #pragma unroll
        for (int m = 0; m < 32; ++m) z[slotof(np + m * 512)] = v[m];
    }
    __syncthreads();

    // ============ forward group B: 5 bits, stride 16 within 512-blocks ====
    // passes: radix-4 L=128, radix-4 L=32, radix-2 L=16
    {
        const int lane = tid & 15;
        const int base = (tid >> 4) * 512 + lane;
        #pragma unroll
        for (int m = 0; m < 32; ++m) v[m] = z[slotof(base + m * 16)];
        #pragma unroll
        for (int m0 = 0; m0 < 8; ++m0)
            dif_bfly(v[m0], v[m0 + 8], v[m0 + 16], v[m0 + 24],
                     tw[(lane + m0 * 16) << 5]);
        #pragma unroll
        for (int mb = 0; mb < 32; mb += 8)
            #pragma unroll
            for (int m0 = 0; m0 < 2; ++m0)
                dif_bfly(v[mb + m0], v[mb + m0 + 2], v[mb + m0 + 4],
                         v[mb + m0 + 6], tw[(lane + m0 * 16) << 7]);
        {
            float2 w = twr2(tw, lane << 9);
            #pragma unroll
            for (int m = 0; m < 32; m += 2) dif2(v[m], v[m + 1], w);
        }
        #pragma unroll
        for (int m = 0; m < 32; ++m) z[slotof(base + m * 16)] = v[m];
    }
    // exchange with group C is confined to 16 threads of the same warp
    __syncwarp();

    // ==== fused: group C (two 16-pt FFTs) -> pointwise -> group C' ====
    // Own 32-block starts at float2-slot 34*tid (16B-aligned): float4 ops.
    {
        const int f4base = 17 * tid;     // float4 index of own block
        #pragma unroll
        for (int j = 0; j < 16; ++j) {
            float4 q = z4[f4base + j];
            v[2 * j]     = make_float2(q.x, q.y);
            v[2 * j + 1] = make_float2(q.z, q.w);
        }
        fwd16(v);
        fwd16(v + 16);
        // publish forward output so other threads can read partners
        #pragma unroll
        for (int j = 0; j < 16; ++j)
            z4[f4base + j] = make_float4(v[2 * j].x, v[2 * j].y,
                                         v[2 * j + 1].x, v[2 * j + 1].y);
        __syncthreads();

        // Hermitian split + pointwise product (1/N folded into f2 scale).
        // Position j holds Z[k], k = rho(j); partner holds Z[(N-k) mod N].
        // For khi = rho(32*tid) != 0: partner(ibase+m) = pbase + (31-m),
        // pbase = rho(512 - khi) (contiguous, 32-aligned).
        const float CI = 0.5f / (float)N_FFT;   // exact power of 2
        if (tid != 0) {
            const int khi = rho(32 * tid);
            const int pb  = rho(512 - khi);        // 32-aligned block base
            const int pf4 = 17 * (pb >> 5);        // float4 index of partner
            #pragma unroll
            for (int jj = 0; jj < 16; ++jj) {
                float4 pq = z4[pf4 + 15 - jj];
                // own element 2jj pairs with partner element 31-2jj (high),
                // own element 2jj+1 pairs with 30-2jj (low)
                float2 A0 = v[2 * jj];
                float2 B0 = make_float2(pq.z, pq.w);
                float2 A1 = v[2 * jj + 1];
                float2 B1 = make_float2(pq.x, pq.y);
                {
                    float f1r = 0.5f * (A0.x + B0.x);
                    float f1i = 0.5f * (A0.y - B0.y);
                    float f2r = CI * (A0.y + B0.y);
                    float f2i = CI * (B0.x - A0.x);
                    v[2 * jj] = make_float2(f1r * f2r - f1i * f2i,
                                            f1r * f2i + f1i * f2r);
                }
                {
                    float f1r = 0.5f * (A1.x + B1.x);
                    float f1i = 0.5f * (A1.y - B1.y);
                    float f2r = CI * (A1.y + B1.y);
                    float f2i = CI * (B1.x - A1.x);
                    v[2 * jj + 1] = make_float2(f1r * f2r - f1i * f2i,
                                                f1r * f2i + f1i * f2r);
                }
            }
        } else {
            // block 0 partners itself; general per-element path
            #pragma unroll
            for (int m = 0; m < 32; ++m) {
                int k  = rho(m);
                int nk = (N_FFT - k) & (N_FFT - 1);
                int pj = rho(nk);
                float2 A  = v[m];
                float2 Bv = z[slotof(pj)];
                float f1r = 0.5f * (A.x + Bv.x);
                float f1i = 0.5f * (A.y - Bv.y);
                float f2r = CI * (A.y + Bv.y);
                float f2i = CI * (Bv.x - A.x);
                v[m] = make_float2(f1r * f2r - f1i * f2i,
                                   f1r * f2i + f1i * f2r);
            }
        }
        __syncthreads();   // all partner reads done before anyone overwrites z

        inv16(v);
        inv16(v + 16);
        #pragma unroll
        for (int j = 0; j < 16; ++j)
            z4[f4base + j] = make_float4(v[2 * j].x, v[2 * j].y,
                                         v[2 * j + 1].x, v[2 * j + 1].y);
    }
    // exchange with group B' is warp-local
    __syncwarp();

    // ============ inverse group B' ============
    {
        const int lane = tid & 15;
        const int base = (tid >> 4) * 512 + lane;
        #pragma unroll
        for (int m = 0; m < 32; ++m) v[m] = z[slotof(base + m * 16)];
        {
            float2 wc = cconj(twr2(tw, lane << 9));
            #pragma unroll
            for (int m = 0; m < 32; m += 2) dit2(v[m], v[m + 1], wc);
        }
        #pragma unroll
        for (int mb = 0; mb < 32; mb += 8)
            #pragma unroll
            for (int m0 = 0; m0 < 2; ++m0)
                dit_bfly(v[mb + m0], v[mb + m0 + 2], v[mb + m0 + 4],
                         v[mb + m0 + 6], cconj(tw[(lane + m0 * 16) << 7]));
        #pragma unroll
        for (int m0 = 0; m0 < 8; ++m0)
            dit_bfly(v[m0], v[m0 + 8], v[m0 + 16], v[m0 + 24],
                     cconj(tw[(lane + m0 * 16) << 5]));
        #pragma unroll
        for (int m = 0; m < 32; ++m) z[slotof(base + m * 16)] = v[m];
    }
    __syncthreads();

    // ============ inverse group A' + fused gmem epilogue ============
    {
        const int np = tid;
        #pragma unroll
        for (int m = 0; m < 32; ++m) v[m] = z[slotof(np + m * 512)];
        {
            float2 wc = cconj(twr2(tw, np << 4));
            #pragma unroll
            for (int m = 0; m < 32; m += 2) dit2(v[m], v[m + 1], wc);
        }
        #pragma unroll
        for (int mb = 0; mb < 32; mb += 8)
            #pragma unroll
            for (int m0 = 0; m0 < 2; ++m0)
                dit_bfly(v[mb + m0], v[mb + m0 + 2], v[mb + m0 + 4],
                         v[mb + m0 + 6], cconj(tw[(np + m0 * 512) << 2]));
        #pragma unroll
        for (int m0 = 0; m0 < 8; ++m0)
            dit_bfly(v[m0], v[m0 + 8], v[m0 + 16], v[m0 + 24],
                     cconj(tw[np + m0 * 512]));

        float* outr = out + (size_t)b * N_FFT;
        #pragma unroll
        for (int m = 0; m < 32; ++m)
            outr[np + m * 512] = v[m].x;        // 1/N already folded in
    }
}

extern "C" void kernel_launch(void* const* d_in, const int* in_sizes, int n_in,
                              void* d_out, int out_size)
{
    const float* x1 = (const float*)d_in[0];
    const float* x2 = (const float*)d_in[1];
    const int*   h1 = (const int*)  d_in[2];
    const float* s1 = (const float*)d_in[3];
    float*       out = (float*)d_out;

    const int smem_bytes = (Z_SLOTS + TW_N) * (int)sizeof(float2);  // 172032
    cudaFuncSetAttribute(cbp_fft32d_kernel,
                         cudaFuncAttributeMaxDynamicSharedMemorySize,
                         smem_bytes);

    const int batch = out_size / N_FFT;   // 256
    cbp_fft32d_kernel<<<batch, NTHREADS, smem_bytes>>>(x1, x2, h1, s1, out);
}

// round 9
// speedup vs baseline: 4.5620x; 1.1449x over previous
#include <cuda_runtime.h>
#include <cuda_bf16.h>

// CompactBilinearPooling: count-sketch into O=16384 buckets + circular conv
// via FFT. One CTA per batch row, 512 threads, 32 elements per thread.
// Forward: radix-32 (stride 512), radix-32 (stride 16), radix-16 (contig)
// DIF groups. Strided radix-32 groups load only 3 base twiddles from smem
// and derive the rest by constant rotation (32nd roots as immediates).
// Pointwise Hermitian product fused with the last forward and first inverse
// group in registers; partner indices in closed form. 1/N folded in.

#define N_FFT    16384
#define LOG2N    14
#define D_IN     4096
#define NTHREADS 512
#define TW_N     4096
#define Z_SLOTS  17408   // slot(16383)=16383+2*511=17405, rounded to /4

__device__ __forceinline__ int slotof(int i) { return i + 2 * (i >> 5); }

// packed fp32x2 add/sub (sm_103a)
__device__ __forceinline__ float2 cadd(float2 a, float2 b) {
    float2 r;
    asm("{\n\t.reg .b64 ra, rb, rc;\n\t"
        "mov.b64 ra, {%2,%3};\n\t"
        "mov.b64 rb, {%4,%5};\n\t"
        "add.rn.f32x2 rc, ra, rb;\n\t"
        "mov.b64 {%0,%1}, rc;\n\t}"
        : "=f"(r.x), "=f"(r.y)
        : "f"(a.x), "f"(a.y), "f"(b.x), "f"(b.y));
    return r;
}
__device__ __forceinline__ float2 csub(float2 a, float2 b) {
    float2 r;
    asm("{\n\t.reg .b64 ra, rb, rc;\n\t"
        "mov.b64 ra, {%2,%3};\n\t"
        "mov.b64 rb, {%4,%5};\n\t"
        "sub.rn.f32x2 rc, ra, rb;\n\t"
        "mov.b64 {%0,%1}, rc;\n\t}"
        : "=f"(r.x), "=f"(r.y)
        : "f"(a.x), "f"(a.y), "f"(b.x), "f"(b.y));
    return r;
}
__device__ __forceinline__ float2 cmul(float2 a, float2 b) {
    return make_float2(fmaf(a.x, b.x, -a.y * b.y),
                       fmaf(a.x, b.y,  a.y * b.x));
}
__device__ __forceinline__ float2 cconj(float2 a) {
    return make_float2(a.x, -a.y);
}
// w * (c + i s) with c, s immediates
__device__ __forceinline__ float2 twmul(float2 w, float c, float s) {
    return make_float2(fmaf(w.x, c, -w.y * s), fmaf(w.x, s, w.y * c));
}

// twiddle fetch for indices in [0, 8192): table holds k < 4096;
// w^(4096+r) = -i * w^r = (s, -c)
__device__ __forceinline__ float2 twr2(const float2* tw, int idx) {
    float2 t = tw[idx & (TW_N - 1)];
    return (idx & TW_N) ? make_float2(t.y, -t.x) : t;
}

// position <-> frequency involution for digit pattern [2,2,1,2,2,1,2,2]:
// 14-bit reverse, then swap adjacent bit pairs at {0,2,5,7,10,12}; bits 4,9 fixed.
__device__ __forceinline__ int rho(int j) {
    unsigned b = __brev((unsigned)j) >> (32 - LOG2N);
    return (int)(((b & 0x14A5u) << 1) | ((b >> 1) & 0x14A5u) | (b & 0x0210u));
}

// radix-4 DIF butterfly; post-twiddle by w^q (w1 in registers)
__device__ __forceinline__ void dif_bfly(float2& a0, float2& a1, float2& a2,
                                         float2& a3, float2 w1) {
    float2 w2 = cmul(w1, w1), w3 = cmul(w2, w1);
    float2 t0 = cadd(a0, a2), t1 = csub(a0, a2);
    float2 t2 = cadd(a1, a3), t3 = csub(a1, a3);
    float2 y0 = cadd(t0, t2);
    float2 y2 = csub(t0, t2);
    float2 y1 = make_float2(t1.x + t3.y, t1.y - t3.x);   // t1 - i*t3
    float2 y3 = make_float2(t1.x - t3.y, t1.y + t3.x);   // t1 + i*t3
    a0 = y0;
    a1 = cmul(y1, w1);
    a2 = cmul(y2, w2);
    a3 = cmul(y3, w3);
}
// radix-4 DIF with all three twiddles given (immediates)
__device__ __forceinline__ void dif_w(float2& a0, float2& a1, float2& a2,
                                      float2& a3, float2 w1, float2 w2,
                                      float2 w3) {
    float2 t0 = cadd(a0, a2), t1 = csub(a0, a2);
    float2 t2 = cadd(a1, a3), t3 = csub(a1, a3);
    float2 y0 = cadd(t0, t2);
    float2 y2 = csub(t0, t2);
    float2 y1 = make_float2(t1.x + t3.y, t1.y - t3.x);
    float2 y3 = make_float2(t1.x - t3.y, t1.y + t3.x);
    a0 = y0;
    a1 = cmul(y1, w1);
    a2 = cmul(y2, w2);
    a3 = cmul(y3, w3);
}
// radix-4 DIF, w == 1
__device__ __forceinline__ void dif_nt(float2& a0, float2& a1, float2& a2,
                                       float2& a3) {
    float2 t0 = cadd(a0, a2), t1 = csub(a0, a2);
    float2 t2 = cadd(a1, a3), t3 = csub(a1, a3);
    a0 = cadd(t0, t2);
    a2 = csub(t0, t2);
    a1 = make_float2(t1.x + t3.y, t1.y - t3.x);
    a3 = make_float2(t1.x - t3.y, t1.y + t3.x);
}

// radix-4 DIT butterfly (pre-twiddle by conj w^q); w1c already conjugated
__device__ __forceinline__ void dit_bfly(float2& a0, float2& a1, float2& a2,
                                         float2& a3, float2 w1c) {
    float2 w2 = cmul(w1c, w1c), w3 = cmul(w2, w1c);
    float2 t1 = cmul(a1, w1c), t2 = cmul(a2, w2), t3 = cmul(a3, w3);
    float2 e0 = cadd(a0, t2), e1 = csub(a0, t2);
    float2 e2 = cadd(t1, t3), e3 = csub(t1, t3);
    a0 = cadd(e0, e2);
    a1 = make_float2(e1.x - e3.y, e1.y + e3.x);          // e1 + i*e3
    a2 = csub(e0, e2);
    a3 = make_float2(e1.x + e3.y, e1.y - e3.x);          // e1 - i*e3
}
// radix-4 DIT with all three conj twiddles given (immediates)
__device__ __forceinline__ void dit_w(float2& a0, float2& a1, float2& a2,
                                      float2& a3, float2 w1c, float2 w2c,
                                      float2 w3c) {
    float2 t1 = cmul(a1, w1c), t2 = cmul(a2, w2c), t3 = cmul(a3, w3c);
    float2 e0 = cadd(a0, t2), e1 = csub(a0, t2);
    float2 e2 = cadd(t1, t3), e3 = csub(t1, t3);
    a0 = cadd(e0, e2);
    a1 = make_float2(e1.x - e3.y, e1.y + e3.x);
    a2 = csub(e0, e2);
    a3 = make_float2(e1.x + e3.y, e1.y - e3.x);
}
// radix-4 DIT, w == 1
__device__ __forceinline__ void dit_nt(float2& a0, float2& a1, float2& a2,
                                       float2& a3) {
    float2 e0 = cadd(a0, a2), e1 = csub(a0, a2);
    float2 e2 = cadd(a1, a3), e3 = csub(a1, a3);
    a0 = cadd(e0, e2);
    a1 = make_float2(e1.x - e3.y, e1.y + e3.x);
    a2 = csub(e0, e2);
    a3 = make_float2(e1.x + e3.y, e1.y - e3.x);
}

// radix-2 DIF: a'=a+b, b'=(a-b)w
__device__ __forceinline__ void dif2(float2& a, float2& b, float2 w) {
    float2 s = cadd(a, b), d = csub(a, b);
    a = s;
    b = cmul(d, w);
}
// radix-2 DIT: t=b*wc; a'=a+t, b'=a-t
__device__ __forceinline__ void dit2(float2& a, float2& b, float2 wc) {
    float2 t = cmul(b, wc);
    b = csub(a, t);
    a = cadd(a, t);
}

// twiddle constants
#define C16A 0.92387953251128674f   // cos(pi/8)
#define S16A 0.38268343236508978f   // sin(pi/8)
#define RS2  0.70710678118654752f   // 1/sqrt(2)
#define C32A 0.98078528040323044f   // cos(pi/16)
#define S32A 0.19509032201612827f   // sin(pi/16)
#define C32B 0.83146961230254524f   // cos(3pi/16)
#define S32B 0.55557023301960218f   // sin(3pi/16)

// 32-point DIF on v[0..31] (element m at logical stride L/8), given base
// twiddles: w1 = tw[n], w2 = tw[4n], wr = tw[16n] (appropriately scaled
// indices at the call site). Layer-1 twiddle for slot m is
// tw[n + m*(N/32-scale)] = w1 * exp(-i*pi*m/16)  -> constant rotations.
__device__ __forceinline__ void fwd32(float2* v, float2 w1, float2 w2,
                                      float2 wr) {
    dif_bfly(v[0], v[8], v[16], v[24], w1);
    dif_bfly(v[1], v[9], v[17], v[25], twmul(w1, C32A, -S32A));
    dif_bfly(v[2], v[10], v[18], v[26], twmul(w1, C16A, -S16A));
    dif_bfly(v[3], v[11], v[19], v[27], twmul(w1, C32B, -S32B));
    dif_bfly(v[4], v[12], v[20], v[28], twmul(w1, RS2,  -RS2));
    dif_bfly(v[5], v[13], v[21], v[29], twmul(w1, S32B, -C32B));
    dif_bfly(v[6], v[14], v[22], v[30], twmul(w1, S16A, -C16A));
    dif_bfly(v[7], v[15], v[23], v[31], twmul(w1, S32A, -C32A));
    float2 w2b = twmul(w2, RS2, -RS2);
    #pragma unroll
    for (int mb = 0; mb < 32; mb += 8) {
        dif_bfly(v[mb],     v[mb + 2], v[mb + 4], v[mb + 6], w2);
        dif_bfly(v[mb + 1], v[mb + 3], v[mb + 5], v[mb + 7], w2b);
    }
    #pragma unroll
    for (int m = 0; m < 32; m += 2) dif2(v[m], v[m + 1], wr);
}
// inverse: all base twiddles already conjugated
__device__ __forceinline__ void inv32(float2* v, float2 w1c, float2 w2c,
                                      float2 wrc) {
    #pragma unroll
    for (int m = 0; m < 32; m += 2) dit2(v[m], v[m + 1], wrc);
    float2 w2bc = twmul(w2c, RS2, RS2);
    #pragma unroll
    for (int mb = 0; mb < 32; mb += 8) {
        dit_bfly(v[mb],     v[mb + 2], v[mb + 4], v[mb + 6], w2c);
        dit_bfly(v[mb + 1], v[mb + 3], v[mb + 5], v[mb + 7], w2bc);
    }
    dit_bfly(v[0], v[8], v[16], v[24], w1c);
    dit_bfly(v[1], v[9], v[17], v[25], twmul(w1c, C32A, S32A));
    dit_bfly(v[2], v[10], v[18], v[26], twmul(w1c, C16A, S16A));
    dit_bfly(v[3], v[11], v[19], v[27], twmul(w1c, C32B, S32B));
    dit_bfly(v[4], v[12], v[20], v[28], twmul(w1c, RS2,  RS2));
    dit_bfly(v[5], v[13], v[21], v[29], twmul(w1c, S32B, C32B));
    dit_bfly(v[6], v[14], v[22], v[30], twmul(w1c, S16A, C16A));
    dit_bfly(v[7], v[15], v[23], v[31], twmul(w1c, S32A, C32A));
}

// 16-point DIF/DIT on contiguous register elements, all-immediate twiddles
__device__ __forceinline__ void fwd16(float2* v) {
    dif_nt(v[0], v[4], v[8], v[12]);
    dif_w(v[1], v[5], v[9], v[13],
          make_float2( C16A, -S16A), make_float2( RS2, -RS2),
          make_float2( S16A, -C16A));
    dif_w(v[2], v[6], v[10], v[14],
          make_float2( RS2, -RS2), make_float2(0.0f, -1.0f),
          make_float2(-RS2, -RS2));
    dif_w(v[3], v[7], v[11], v[15],
          make_float2( S16A, -C16A), make_float2(-RS2, -RS2),
          make_float2(-C16A,  S16A));
    #pragma unroll
    for (int q = 0; q < 4; ++q)
        dif_nt(v[4 * q], v[4 * q + 1], v[4 * q + 2], v[4 * q + 3]);
}
__device__ __forceinline__ void inv16(float2* v) {
    #pragma unroll
    for (int q = 0; q < 4; ++q)
        dit_nt(v[4 * q], v[4 * q + 1], v[4 * q + 2], v[4 * q + 3]);
    dit_nt(v[0], v[4], v[8], v[12]);
    dit_w(v[1], v[5], v[9], v[13],
          make_float2( C16A,  S16A), make_float2( RS2,  RS2),
          make_float2( S16A,  C16A));
    dit_w(v[2], v[6], v[10], v[14],
          make_float2( RS2,  RS2), make_float2(0.0f, 1.0f),
          make_float2(-RS2,  RS2));
    dit_w(v[3], v[7], v[11], v[15],
          make_float2( S16A,  C16A), make_float2(-RS2,  RS2),
          make_float2(-C16A, -S16A));
}

__global__ __launch_bounds__(NTHREADS, 1)
void cbp_fft32e_kernel(const float* __restrict__ x1,
                       const float* __restrict__ x2,
                       const int*   __restrict__ h1,
                       const float* __restrict__ s1,
                       float*       __restrict__ out)
{
    extern __shared__ float2 smem[];
    float2* z  = smem;              // padded work array
    float2* tw = smem + Z_SLOTS;    // [TW_N] exp(-i*pi*k/8192), k < N/4
    float4* z4 = reinterpret_cast<float4*>(smem);

    const int tid = threadIdx.x;
    const int b   = blockIdx.x;

    // --- prefetch inputs (hide DRAM latency behind twiddle gen + zeroing) ---
    float4 pa1[2], pa2[2], pss[2];
    int4   phh[2];
    {
        const float4* x1v = reinterpret_cast<const float4*>(x1 + (size_t)b * D_IN);
        const float4* x2v = reinterpret_cast<const float4*>(x2 + (size_t)b * D_IN);
        const int4*   h1v = reinterpret_cast<const int4*>(h1);
        const float4* s1v = reinterpret_cast<const float4*>(s1);
        #pragma unroll
        for (int it = 0; it < 2; ++it) {
            int idx = tid + it * NTHREADS;
            pa1[it] = x1v[idx];
            pa2[it] = x2v[idx];
            phh[it] = h1v[idx];
            pss[it] = s1v[idx];
        }
    }

    // --- twiddles: 4 sincospif + 4 derived via w^(k+2048) = w^k * e^{-i pi/4}
    {
        const float2 c8 = make_float2(RS2, -RS2);
        #pragma unroll
        for (int it = 0; it < 4; ++it) {
            int k = tid + it * NTHREADS;     // k < 2048
            float s, c;
            sincospif(-(float)k * (1.0f / 8192.0f), &s, &c);
            float2 w = make_float2(c, s);
            tw[k]        = w;
            tw[k + 2048] = cmul(w, c8);
        }
    }
    // --- zero the padded work array (float4 stores) ---
    #pragma unroll
    for (int i = tid; i < Z_SLOTS / 2; i += NTHREADS)
        z4[i] = make_float4(0.0f, 0.0f, 0.0f, 0.0f);
    __syncthreads();

    // --- count-sketch scatter from prefetched registers ---
    #pragma unroll
    for (int it = 0; it < 2; ++it) {
        float4 a1 = pa1[it];
        float4 a2 = pa2[it];
        int4   hh = phh[it];
        float4 ss = pss[it];
        int s0 = slotof(hh.x), s1i = slotof(hh.y);
        int s2 = slotof(hh.z), s3 = slotof(hh.w);
        atomicAdd(&z[s0].x,  ss.x * a1.x);
        atomicAdd(&z[s0].y,  ss.x * a2.x);
        atomicAdd(&z[s1i].x, ss.y * a1.y);
        atomicAdd(&z[s1i].y, ss.y * a2.y);
        atomicAdd(&z[s2].x,  ss.z * a1.z);
        atomicAdd(&z[s2].y,  ss.z * a2.z);
        atomicAdd(&z[s3].x,  ss.w * a1.w);
        atomicAdd(&z[s3].y,  ss.w * a2.w);
    }
    __syncthreads();

    float2 v[32];

    // ============ forward group A: 5 bits, stride 512 ============
    {
        const int np = tid;
        #pragma unroll
        for (int m = 0; m < 32; ++m) v[m] = z[slotof(np + m * 512)];
        fwd32(v, tw[np], tw[np << 2], twr2(tw, np << 4));
        #pragma unroll
        for (int m = 0; m < 32; ++m) z[slotof(np + m * 512)] = v[m];
    }
    __syncthreads();

    // ============ forward group B: 5 bits, stride 16 within 512-blocks ====
    {
        const int lane = tid & 15;
        const int base = (tid >> 4) * 512 + lane;
        #pragma unroll
        for (int m = 0; m < 32; ++m) v[m] = z[slotof(base + m * 16)];
        fwd32(v, tw[lane << 5], tw[lane << 7], twr2(tw, lane << 9));
        #pragma unroll
        for (int m = 0; m < 32; ++m) z[slotof(base + m * 16)] = v[m];
    }
    // exchange with group C is confined to 16 threads of the same warp
    __syncwarp();

    // ==== fused: group C (two 16-pt FFTs) -> pointwise -> group C' ====
    // Own 32-block starts at float2-slot 34*tid (16B-aligned): float4 ops.
    {
        const int f4base = 17 * tid;     // float4 index of own block
        #pragma unroll
        for (int j = 0; j < 16; ++j) {
            float4 q = z4[f4base + j];
            v[2 * j]     = make_float2(q.x, q.y);
            v[2 * j + 1] = make_float2(q.z, q.w);
        }
        fwd16(v);
        fwd16(v + 16);
        // publish forward output so other threads can read partners
        #pragma unroll
        for (int j = 0; j < 16; ++j)
            z4[f4base + j] = make_float4(v[2 * j].x, v[2 * j].y,
                                         v[2 * j + 1].x, v[2 * j + 1].y);
        __syncthreads();

        // Hermitian split + pointwise product (1/N folded into f2 scale).
        // Position j holds Z[k], k = rho(j); partner holds Z[(N-k) mod N].
        // For khi = rho(32*tid) != 0: partner(ibase+m) = pbase + (31-m),
        // pbase = rho(512 - khi) (contiguous, 32-aligned).
        const float CI = 0.5f / (float)N_FFT;   // exact power of 2
        if (tid != 0) {
            const int khi = rho(32 * tid);
            const int pb  = rho(512 - khi);        // 32-aligned block base
            const int pf4 = 17 * (pb >> 5);        // float4 index of partner
            #pragma unroll
            for (int jj = 0; jj < 16; ++jj) {
                float4 pq = z4[pf4 + 15 - jj];
                float2 A0 = v[2 * jj];
                float2 B0 = make_float2(pq.z, pq.w);
                float2 A1 = v[2 * jj + 1];
                float2 B1 = make_float2(pq.x, pq.y);
                {
                    float f1r = 0.5f * (A0.x + B0.x);
                    float f1i = 0.5f * (A0.y - B0.y);
                    float f2r = CI * (A0.y + B0.y);
                    float f2i = CI * (B0.x - A0.x);
                    v[2 * jj] = make_float2(f1r * f2r - f1i * f2i,
                                            f1r * f2i + f1i * f2r);
                }
                {
                    float f1r = 0.5f * (A1.x + B1.x);
                    float f1i = 0.5f * (A1.y - B1.y);
                    float f2r = CI * (A1.y + B1.y);
                    float f2i = CI * (B1.x - A1.x);
                    v[2 * jj + 1] = make_float2(f1r * f2r - f1i * f2i,
                                                f1r * f2i + f1i * f2r);
                }
            }
        } else {
            // block 0 partners itself; general per-element path
            #pragma unroll
            for (int m = 0; m < 32; ++m) {
                int k  = rho(m);
                int nk = (N_FFT - k) & (N_FFT - 1);
                int pj = rho(nk);
                float2 A  = v[m];
                float2 Bv = z[slotof(pj)];
                float f1r = 0.5f * (A.x + Bv.x);
                float f1i = 0.5f * (A.y - Bv.y);
                float f2r = CI * (A.y + Bv.y);
                float f2i = CI * (Bv.x - A.x);
                v[m] = make_float2(f1r * f2r - f1i * f2i,
                                   f1r * f2i + f1i * f2r);
            }
        }
        __syncthreads();   // all partner reads done before anyone overwrites z

        inv16(v);
        inv16(v + 16);
        #pragma unroll
        for (int j = 0; j < 16; ++j)
            z4[f4base + j] = make_float4(v[2 * j].x, v[2 * j].y,
                                         v[2 * j + 1].x, v[2 * j + 1].y);
    }
    // exchange with group B' is warp-local
    __syncwarp();

    // ============ inverse group B' ============
    {
        const int lane = tid & 15;
        const int base = (tid >> 4) * 512 + lane;
        #pragma unroll
        for (int m = 0; m < 32; ++m) v[m] = z[slotof(base + m * 16)];
        inv32(v, cconj(tw[lane << 5]), cconj(tw[lane << 7]),
              cconj(twr2(tw, lane << 9)));
        #pragma unroll
        for (int m = 0; m < 32; ++m) z[slotof(base + m * 16)] = v[m];
    }
    __syncthreads();

    // ============ inverse group A' + fused gmem epilogue ============
    {
        const int np = tid;
        #pragma unroll
        for (int m = 0; m < 32; ++m) v[m] = z[slotof(np + m * 512)];
        inv32(v, cconj(tw[np]), cconj(tw[np << 2]), cconj(twr2(tw, np << 4)));
        float* outr = out + (size_t)b * N_FFT;
        #pragma unroll
        for (int m = 0; m < 32; ++m)
            outr[np + m * 512] = v[m].x;        // 1/N already folded in
    }
}

extern "C" void kernel_launch(void* const* d_in, const int* in_sizes, int n_in,
                              void* d_out, int out_size)
{
    const float* x1 = (const float*)d_in[0];
    const float* x2 = (const float*)d_in[1];
    const int*   h1 = (const int*)  d_in[2];
    const float* s1 = (const float*)d_in[3];
    float*       out = (float*)d_out;

    const int smem_bytes = (Z_SLOTS + TW_N) * (int)sizeof(float2);  // 172032
    cudaFuncSetAttribute(cbp_fft32e_kernel,
                         cudaFuncAttributeMaxDynamicSharedMemorySize,
                         smem_bytes);

    const int batch = out_size / N_FFT;   // 256
    cbp_fft32e_kernel<<<batch, NTHREADS, smem_bytes>>>(x1, x2, h1, s1, out);
}

// round 10
// speedup vs baseline: 4.6990x; 1.0300x over previous
#include <cuda_runtime.h>
#include <cuda_bf16.h>

// CompactBilinearPooling: count-sketch into O=16384 buckets + circular conv
// via FFT. One CTA per batch row, 512 threads, 32 elements per thread.
// Forward: radix-32 (stride 512), radix-32 (stride 16), radix-16 (contig)
// DIF groups; all twiddle powers hoisted/derived by constant rotation (32nd
// roots as immediates), only 3 smem twiddle loads per strided group.
// Pointwise Hermitian product fused with the last forward and first inverse
// group in registers; partner indices in closed form. 1/N folded in.

#define N_FFT    16384
#define LOG2N    14
#define D_IN     4096
#define NTHREADS 512
#define TW_N     4096
#define Z_SLOTS  17408   // slot(16383)=16383+2*511=17405, rounded to /4

__device__ __forceinline__ int slotof(int i) { return i + 2 * (i >> 5); }

// packed fp32x2 add/sub (sm_103a)
__device__ __forceinline__ float2 cadd(float2 a, float2 b) {
    float2 r;
    asm("{\n\t.reg .b64 ra, rb, rc;\n\t"
        "mov.b64 ra, {%2,%3};\n\t"
        "mov.b64 rb, {%4,%5};\n\t"
        "add.rn.f32x2 rc, ra, rb;\n\t"
        "mov.b64 {%0,%1}, rc;\n\t}"
        : "=f"(r.x), "=f"(r.y)
        : "f"(a.x), "f"(a.y), "f"(b.x), "f"(b.y));
    return r;
}
__device__ __forceinline__ float2 csub(float2 a, float2 b) {
    float2 r;
    asm("{\n\t.reg .b64 ra, rb, rc;\n\t"
        "mov.b64 ra, {%2,%3};\n\t"
        "mov.b64 rb, {%4,%5};\n\t"
        "sub.rn.f32x2 rc, ra, rb;\n\t"
        "mov.b64 {%0,%1}, rc;\n\t}"
        : "=f"(r.x), "=f"(r.y)
        : "f"(a.x), "f"(a.y), "f"(b.x), "f"(b.y));
    return r;
}
__device__ __forceinline__ float2 cmul(float2 a, float2 b) {
    return make_float2(fmaf(a.x, b.x, -a.y * b.y),
                       fmaf(a.x, b.y,  a.y * b.x));
}
__device__ __forceinline__ float2 cconj(float2 a) {
    return make_float2(a.x, -a.y);
}
// w * (c + i s) with c, s immediates
__device__ __forceinline__ float2 twmul(float2 w, float c, float s) {
    return make_float2(fmaf(w.x, c, -w.y * s), fmaf(w.x, s, w.y * c));
}

// twiddle fetch for indices in [0, 8192): table holds k < 4096;
// w^(4096+r) = -i * w^r = (s, -c)
__device__ __forceinline__ float2 twr2(const float2* tw, int idx) {
    float2 t = tw[idx & (TW_N - 1)];
    return (idx & TW_N) ? make_float2(t.y, -t.x) : t;
}

// position <-> frequency involution for digit pattern [2,2,1,2,2,1,2,2]:
// 14-bit reverse, then swap adjacent bit pairs at {0,2,5,7,10,12}; bits 4,9 fixed.
__device__ __forceinline__ int rho(int j) {
    unsigned b = __brev((unsigned)j) >> (32 - LOG2N);
    return (int)(((b & 0x14A5u) << 1) | ((b >> 1) & 0x14A5u) | (b & 0x0210u));
}

// radix-4 DIF with all three twiddles given
__device__ __forceinline__ void dif_w(float2& a0, float2& a1, float2& a2,
                                      float2& a3, float2 w1, float2 w2,
                                      float2 w3) {
    float2 t0 = cadd(a0, a2), t1 = csub(a0, a2);
    float2 t2 = cadd(a1, a3), t3 = csub(a1, a3);
    float2 y0 = cadd(t0, t2);
    float2 y2 = csub(t0, t2);
    float2 y1 = make_float2(t1.x + t3.y, t1.y - t3.x);   // t1 - i*t3
    float2 y3 = make_float2(t1.x - t3.y, t1.y + t3.x);   // t1 + i*t3
    a0 = y0;
    a1 = cmul(y1, w1);
    a2 = cmul(y2, w2);
    a3 = cmul(y3, w3);
}
// radix-4 DIF, w == 1
__device__ __forceinline__ void dif_nt(float2& a0, float2& a1, float2& a2,
                                       float2& a3) {
    float2 t0 = cadd(a0, a2), t1 = csub(a0, a2);
    float2 t2 = cadd(a1, a3), t3 = csub(a1, a3);
    a0 = cadd(t0, t2);
    a2 = csub(t0, t2);
    a1 = make_float2(t1.x + t3.y, t1.y - t3.x);
    a3 = make_float2(t1.x - t3.y, t1.y + t3.x);
}
// radix-4 DIT with all three conj twiddles given
__device__ __forceinline__ void dit_w(float2& a0, float2& a1, float2& a2,
                                      float2& a3, float2 w1c, float2 w2c,
                                      float2 w3c) {
    float2 t1 = cmul(a1, w1c), t2 = cmul(a2, w2c), t3 = cmul(a3, w3c);
    float2 e0 = cadd(a0, t2), e1 = csub(a0, t2);
    float2 e2 = cadd(t1, t3), e3 = csub(t1, t3);
    a0 = cadd(e0, e2);
    a1 = make_float2(e1.x - e3.y, e1.y + e3.x);          // e1 + i*e3
    a2 = csub(e0, e2);
    a3 = make_float2(e1.x + e3.y, e1.y - e3.x);          // e1 - i*e3
}
// radix-4 DIT, w == 1
__device__ __forceinline__ void dit_nt(float2& a0, float2& a1, float2& a2,
                                       float2& a3) {
    float2 e0 = cadd(a0, a2), e1 = csub(a0, a2);
    float2 e2 = cadd(a1, a3), e3 = csub(a1, a3);
    a0 = cadd(e0, e2);
    a1 = make_float2(e1.x - e3.y, e1.y + e3.x);
    a2 = csub(e0, e2);
    a3 = make_float2(e1.x + e3.y, e1.y - e3.x);
}

// radix-2 DIF: a'=a+b, b'=(a-b)w
__device__ __forceinline__ void dif2(float2& a, float2& b, float2 w) {
    float2 s = cadd(a, b), d = csub(a, b);
    a = s;
    b = cmul(d, w);
}
// radix-2 DIT: t=b*wc; a'=a+t, b'=a-t
__device__ __forceinline__ void dit2(float2& a, float2& b, float2 wc) {
    float2 t = cmul(b, wc);
    b = csub(a, t);
    a = cadd(a, t);
}

// twiddle constants
#define C16A 0.92387953251128674f   // cos(pi/8)
#define S16A 0.38268343236508978f   // sin(pi/8)
#define RS2  0.70710678118654752f   // 1/sqrt(2)
#define C32A 0.98078528040323044f   // cos(pi/16)
#define S32A 0.19509032201612827f   // sin(pi/16)
#define C32B 0.83146961230254524f   // cos(3pi/16)
#define S32B 0.55557023301960218f   // sin(3pi/16)

// 32-point DIF on v[0..31]; base twiddles w1=tw[n], w2=tw[4n], wr=tw[16n].
// Layer-1 twiddle for slot m: w1 * e^{-i pi m/16}; its square/cube derived
// from hoisted w1^2, w1^3 by constant rotation. Layer-2 powers hoisted once.
__device__ __forceinline__ void fwd32(float2* v, float2 w1, float2 w2,
                                      float2 wr) {
    float2 w1s = cmul(w1, w1), w1t = cmul(w1s, w1);
    dif_w(v[0], v[8], v[16], v[24], w1, w1s, w1t);
    dif_w(v[1], v[9], v[17], v[25],
          twmul(w1, C32A, -S32A), twmul(w1s, C16A, -S16A),
          twmul(w1t, C32B, -S32B));
    dif_w(v[2], v[10], v[18], v[26],
          twmul(w1, C16A, -S16A), twmul(w1s, RS2, -RS2),
          twmul(w1t, S16A, -C16A));
    dif_w(v[3], v[11], v[19], v[27],
          twmul(w1, C32B, -S32B), twmul(w1s, S16A, -C16A),
          twmul(w1t, -S32A, -C32A));
    dif_w(v[4], v[12], v[20], v[28],
          twmul(w1, RS2, -RS2), twmul(w1s, 0.0f, -1.0f),
          twmul(w1t, -RS2, -RS2));
    dif_w(v[5], v[13], v[21], v[29],
          twmul(w1, S32B, -C32B), twmul(w1s, -S16A, -C16A),
          twmul(w1t, -C32A, -S32A));
    dif_w(v[6], v[14], v[22], v[30],
          twmul(w1, S16A, -C16A), twmul(w1s, -RS2, -RS2),
          twmul(w1t, -C16A, S16A));
    dif_w(v[7], v[15], v[23], v[31],
          twmul(w1, S32A, -C32A), twmul(w1s, -C16A, -S16A),
          twmul(w1t, -S32B, C32B));
    // layer 2: two distinct twiddles; powers hoisted
    float2 w2s = cmul(w2, w2), w2t = cmul(w2s, w2);
    float2 w2b  = twmul(w2, RS2, -RS2);
    float2 w2bs = make_float2(w2s.y, -w2s.x);       // w2s * (0,-1)
    float2 w2bt = twmul(w2t, -RS2, -RS2);
    #pragma unroll
    for (int mb = 0; mb < 32; mb += 8) {
        dif_w(v[mb],     v[mb + 2], v[mb + 4], v[mb + 6], w2, w2s, w2t);
        dif_w(v[mb + 1], v[mb + 3], v[mb + 5], v[mb + 7], w2b, w2bs, w2bt);
    }
    #pragma unroll
    for (int m = 0; m < 32; m += 2) dif2(v[m], v[m + 1], wr);
}
// inverse: base twiddles already conjugated; constants conjugated
__device__ __forceinline__ void inv32(float2* v, float2 w1c, float2 w2c,
                                      float2 wrc) {
    #pragma unroll
    for (int m = 0; m < 32; m += 2) dit2(v[m], v[m + 1], wrc);
    float2 w2cs = cmul(w2c, w2c), w2ct = cmul(w2cs, w2c);
    float2 w2bc  = twmul(w2c, RS2, RS2);
    float2 w2bcs = make_float2(-w2cs.y, w2cs.x);    // w2cs * (0,+1)
    float2 w2bct = twmul(w2ct, -RS2, RS2);
    #pragma unroll
    for (int mb = 0; mb < 32; mb += 8) {
        dit_w(v[mb],     v[mb + 2], v[mb + 4], v[mb + 6], w2c, w2cs, w2ct);
        dit_w(v[mb + 1], v[mb + 3], v[mb + 5], v[mb + 7], w2bc, w2bcs, w2bct);
    }
    float2 w1cs = cmul(w1c, w1c), w1ct = cmul(w1cs, w1c);
    dit_w(v[0], v[8], v[16], v[24], w1c, w1cs, w1ct);
    dit_w(v[1], v[9], v[17], v[25],
          twmul(w1c, C32A, S32A), twmul(w1cs, C16A, S16A),
          twmul(w1ct, C32B, S32B));
    dit_w(v[2], v[10], v[18], v[26],
          twmul(w1c, C16A, S16A), twmul(w1cs, RS2, RS2),
          twmul(w1ct, S16A, C16A));
    dit_w(v[3], v[11], v[19], v[27],
          twmul(w1c, C32B, S32B), twmul(w1cs, S16A, C16A),
          twmul(w1ct, -S32A, C32A));
    dit_w(v[4], v[12], v[20], v[28],
          twmul(w1c, RS2, RS2), twmul(w1cs, 0.0f, 1.0f),
          twmul(w1ct, -RS2, RS2));
    dit_w(v[5], v[13], v[21], v[29],
          twmul(w1c, S32B, C32B), twmul(w1cs, -S16A, C16A),
          twmul(w1ct, -C32A, S32A));
    dit_w(v[6], v[14], v[22], v[30],
          twmul(w1c, S16A, C16A), twmul(w1cs, -RS2, RS2),
          twmul(w1ct, -C16A, -S16A));
    dit_w(v[7], v[15], v[23], v[31],
          twmul(w1c, S32A, C32A), twmul(w1cs, -C16A, S16A),
          twmul(w1ct, -S32B, -C32B));
}

// 16-point DIF/DIT on contiguous register elements, all-immediate twiddles
__device__ __forceinline__ void fwd16(float2* v) {
    dif_nt(v[0], v[4], v[8], v[12]);
    dif_w(v[1], v[5], v[9], v[13],
          make_float2( C16A, -S16A), make_float2( RS2, -RS2),
          make_float2( S16A, -C16A));
    dif_w(v[2], v[6], v[10], v[14],
          make_float2( RS2, -RS2), make_float2(0.0f, -1.0f),
          make_float2(-RS2, -RS2));
    dif_w(v[3], v[7], v[11], v[15],
          make_float2( S16A, -C16A), make_float2(-RS2, -RS2),
          make_float2(-C16A,  S16A));
    #pragma unroll
    for (int q = 0; q < 4; ++q)
        dif_nt(v[4 * q], v[4 * q + 1], v[4 * q + 2], v[4 * q + 3]);
}
__device__ __forceinline__ void inv16(float2* v) {
    #pragma unroll
    for (int q = 0; q < 4; ++q)
        dit_nt(v[4 * q], v[4 * q + 1], v[4 * q + 2], v[4 * q + 3]);
    dit_nt(v[0], v[4], v[8], v[12]);
    dit_w(v[1], v[5], v[9], v[13],
          make_float2( C16A,  S16A), make_float2( RS2,  RS2),
          make_float2( S16A,  C16A));
    dit_w(v[2], v[6], v[10], v[14],
          make_float2( RS2,  RS2), make_float2(0.0f, 1.0f),
          make_float2(-RS2,  RS2));
    dit_w(v[3], v[7], v[11], v[15],
          make_float2( S16A,  C16A), make_float2(-RS2,  RS2),
          make_float2(-C16A, -S16A));
}

__global__ __launch_bounds__(NTHREADS, 1)
void cbp_fft32f_kernel(const float* __restrict__ x1,
                       const float* __restrict__ x2,
                       const int*   __restrict__ h1,
                       const float* __restrict__ s1,
                       float*       __restrict__ out)
{
    extern __shared__ float2 smem[];
    float2* z  = smem;              // padded work array
    float2* tw = smem + Z_SLOTS;    // [TW_N] exp(-i*pi*k/8192), k < N/4
    float4* z4 = reinterpret_cast<float4*>(smem);

    const int tid = threadIdx.x;
    const int b   = blockIdx.x;

    // --- prefetch inputs (hide DRAM latency behind twiddle gen + zeroing) ---
    float4 pa1[2], pa2[2], pss[2];
    int4   phh[2];
    {
        const float4* x1v = reinterpret_cast<const float4*>(x1 + (size_t)b * D_IN);
        const float4* x2v = reinterpret_cast<const float4*>(x2 + (size_t)b * D_IN);
        const int4*   h1v = reinterpret_cast<const int4*>(h1);
        const float4* s1v = reinterpret_cast<const float4*>(s1);
        #pragma unroll
        for (int it = 0; it < 2; ++it) {
            int idx = tid + it * NTHREADS;
            pa1[it] = x1v[idx];
            pa2[it] = x2v[idx];
            phh[it] = h1v[idx];
            pss[it] = s1v[idx];
        }
    }

    // --- twiddles: 2 sincospif, rest derived by constant rotations ---
    // tw[k+1024] = tw[k]*e^{-i pi/8}, tw[k+2048] = tw[k]*e^{-i pi/4},
    // tw[k+3072] = tw[k]*e^{-i 3pi/8}
    {
        const float2 cA = make_float2(C16A, -S16A);
        const float2 cB = make_float2(RS2,  -RS2);
        const float2 cC = make_float2(S16A, -C16A);
        #pragma unroll
        for (int it = 0; it < 2; ++it) {
            int k = tid + it * NTHREADS;     // k < 1024
            float s, c;
            sincospif(-(float)k * (1.0f / 8192.0f), &s, &c);
            float2 w = make_float2(c, s);
            tw[k]        = w;
            tw[k + 1024] = cmul(w, cA);
            tw[k + 2048] = cmul(w, cB);
            tw[k + 3072] = cmul(w, cC);
        }
    }
    // --- zero the padded work array (float4 stores) ---
    #pragma unroll
    for (int i = tid; i < Z_SLOTS / 2; i += NTHREADS)
        z4[i] = make_float4(0.0f, 0.0f, 0.0f, 0.0f);
    __syncthreads();

    // --- count-sketch scatter from prefetched registers ---
    #pragma unroll
    for (int it = 0; it < 2; ++it) {
        float4 a1 = pa1[it];
        float4 a2 = pa2[it];
        int4   hh = phh[it];
        float4 ss = pss[it];
        int s0 = slotof(hh.x), s1i = slotof(hh.y);
        int s2 = slotof(hh.z), s3 = slotof(hh.w);
        atomicAdd(&z[s0].x,  ss.x * a1.x);
        atomicAdd(&z[s0].y,  ss.x * a2.x);
        atomicAdd(&z[s1i].x, ss.y * a1.y);
        atomicAdd(&z[s1i].y, ss.y * a2.y);
        atomicAdd(&z[s2].x,  ss.z * a1.z);
        atomicAdd(&z[s2].y,  ss.z * a2.z);
        atomicAdd(&z[s3].x,  ss.w * a1.w);
        atomicAdd(&z[s3].y,  ss.w * a2.w);
    }
    __syncthreads();

    float2 v[32];

    // ============ forward group A: 5 bits, stride 512 ============
    {
        const int np = tid;
        #pragma unroll
        for (int m = 0; m < 32; ++m) v[m] = z[slotof(np + m * 512)];
        fwd32(v, tw[np], tw[np << 2], twr2(tw, np << 4));
        #pragma unroll
        for (int m = 0; m < 32; ++m) z[slotof(np + m * 512)] = v[m];
    }
    __syncthreads();

    // ============ forward group B: 5 bits, stride 16 within 512-blocks ====
    {
        const int lane = tid & 15;
        const int base = (tid >> 4) * 512 + lane;
        #pragma unroll
        for (int m = 0; m < 32; ++m) v[m] = z[slotof(base + m * 16)];
        fwd32(v, tw[lane << 5], tw[lane << 7], twr2(tw, lane << 9));
        #pragma unroll
        for (int m = 0; m < 32; ++m) z[slotof(base + m * 16)] = v[m];
    }
    // exchange with group C is confined to 16 threads of the same warp
    __syncwarp();

    // ==== fused: group C (two 16-pt FFTs) -> pointwise -> group C' ====
    // Own 32-block starts at float2-slot 34*tid (16B-aligned): float4 ops.
    {
        const int f4base = 17 * tid;     // float4 index of own block
        #pragma unroll
        for (int j = 0; j < 16; ++j) {
            float4 q = z4[f4base + j];
            v[2 * j]     = make_float2(q.x, q.y);
            v[2 * j + 1] = make_float2(q.z, q.w);
        }
        fwd16(v);
        fwd16(v + 16);
        // publish forward output so other threads can read partners
        #pragma unroll
        for (int j = 0; j < 16; ++j)
            z4[f4base + j] = make_float4(v[2 * j].x, v[2 * j].y,
                                         v[2 * j + 1].x, v[2 * j + 1].y);
        __syncthreads();

        // Hermitian split + pointwise product (1/N folded into f2 scale).
        // Position j holds Z[k], k = rho(j); partner holds Z[(N-k) mod N].
        // For khi = rho(32*tid) != 0: partner(ibase+m) = pbase + (31-m),
        // pbase = rho(512 - khi) (contiguous, 32-aligned).
        const float CI = 0.5f / (float)N_FFT;   // exact power of 2
        if (tid != 0) {
            const int khi = rho(32 * tid);
            const int pb  = rho(512 - khi);        // 32-aligned block base
            const int pf4 = 17 * (pb >> 5);        // float4 index of partner
            #pragma unroll
            for (int jj = 0; jj < 16; ++jj) {
                float4 pq = z4[pf4 + 15 - jj];
                float2 A0 = v[2 * jj];
                float2 B0 = make_float2(pq.z, pq.w);
                float2 A1 = v[2 * jj + 1];
                float2 B1 = make_float2(pq.x, pq.y);
                {
                    float f1r = 0.5f * (A0.x + B0.x);
                    float f1i = 0.5f * (A0.y - B0.y);
                    float f2r = CI * (A0.y + B0.y);
                    float f2i = CI * (B0.x - A0.x);
                    v[2 * jj] = make_float2(f1r * f2r - f1i * f2i,
                                            f1r * f2i + f1i * f2r);
                }
                {
                    float f1r = 0.5f * (A1.x + B1.x);
                    float f1i = 0.5f * (A1.y - B1.y);
                    float f2r = CI * (A1.y + B1.y);
                    float f2i = CI * (B1.x - A1.x);
                    v[2 * jj + 1] = make_float2(f1r * f2r - f1i * f2i,
                                                f1r * f2i + f1i * f2r);
                }
            }
        } else {
            // block 0 partners itself; general per-element path
            #pragma unroll
            for (int m = 0; m < 32; ++m) {
                int k  = rho(m);
                int nk = (N_FFT - k) & (N_FFT - 1);
                int pj = rho(nk);
                float2 A  = v[m];
                float2 Bv = z[slotof(pj)];
                float f1r = 0.5f * (A.x + Bv.x);
                float f1i = 0.5f * (A.y - Bv.y);
                float f2r = CI * (A.y + Bv.y);
                float f2i = CI * (Bv.x - A.x);
                v[m] = make_float2(f1r * f2r - f1i * f2i,
                                   f1r * f2i + f1i * f2r);
            }
        }
        __syncthreads();   // all partner reads done before anyone overwrites z

        inv16(v);
        inv16(v + 16);
        #pragma unroll
        for (int j = 0; j < 16; ++j)
            z4[f4base + j] = make_float4(v[2 * j].x, v[2 * j].y,
                                         v[2 * j + 1].x, v[2 * j + 1].y);
    }
    // exchange with group B' is warp-local
    __syncwarp();

    // ============ inverse group B' ============
    {
        const int lane = tid & 15;
        const int base = (tid >> 4) * 512 + lane;
        #pragma unroll
        for (int m = 0; m < 32; ++m) v[m] = z[slotof(base + m * 16)];
        inv32(v, cconj(tw[lane << 5]), cconj(tw[lane << 7]),
              cconj(twr2(tw, lane << 9)));
        #pragma unroll
        for (int m = 0; m < 32; ++m) z[slotof(base + m * 16)] = v[m];
    }
    __syncthreads();

    // ============ inverse group A' + fused gmem epilogue ============
    {
        const int np = tid;
        #pragma unroll
        for (int m = 0; m < 32; ++m) v[m] = z[slotof(np + m * 512)];
        inv32(v, cconj(tw[np]), cconj(tw[np << 2]), cconj(twr2(tw, np << 4)));
        float* outr = out + (size_t)b * N_FFT;
        #pragma unroll
        for (int m = 0; m < 32; ++m)
            outr[np + m * 512] = v[m].x;        // 1/N already folded in
    }
}

extern "C" void kernel_launch(void* const* d_in, const int* in_sizes, int n_in,
                              void* d_out, int out_size)
{
    const float* x1 = (const float*)d_in[0];
    const float* x2 = (const float*)d_in[1];
    const int*   h1 = (const int*)  d_in[2];
    const float* s1 = (const float*)d_in[3];
    float*       out = (float*)d_out;

    const int smem_bytes = (Z_SLOTS + TW_N) * (int)sizeof(float2);  // 172032
    cudaFuncSetAttribute(cbp_fft32f_kernel,
                         cudaFuncAttributeMaxDynamicSharedMemorySize,
                         smem_bytes);

    const int batch = out_size / N_FFT;   // 256
    cbp_fft32f_kernel<<<batch, NTHREADS, smem_bytes>>>(x1, x2, h1, s1, out);
}